// round 11
// baseline (speedup 1.0000x reference)
#include <cuda_runtime.h>
#include <cuda_fp16.h>
#include <math.h>
#include <stdint.h>

// ---------------------------------------------------------------------------
// Problem constants
// ---------------------------------------------------------------------------
#define BATCH    256
#define RESOL    14
#define NTOK     196
#define NQTOK    49
#define INDIM    384
#define HEADS    12
#define KD       16
#define VD       32
#define KVD      576
#define KEYATTN  192
#define VALATTN  384
#define OUTDIM   512
#define ATTNSCALE 0.25f
#define BN_EPS   1e-5f

#define M1 (BATCH*NTOK)   // 50176
#define M2 (BATCH*NQTOK)  // 12544

#define WR_KV 0
#define WR_Q  (576*INDIM)
#define WR_PJ (768*INDIM)

// Scratch (device globals)
__device__ __half g_kvh[(size_t)M1 * KVD];         // fp16 kv
__device__ __half g_qh [(size_t)M2 * KEYATTN];     // fp16 q
__device__ __half g_aoh[(size_t)M2 * VALATTN];     // fp16 attention output
__device__ float  g_btab[(size_t)HEADS * NQTOK * NTOK];
__device__ __half g_xh [(size_t)M1 * INDIM];       // fp16 x
__device__ __half g_wh [(size_t)1280 * INDIM];     // fp16 weights

// ---------------------------------------------------------------------------
// helpers
// ---------------------------------------------------------------------------
__device__ __forceinline__ void mma_f16(float* c, const uint32_t* a, const uint32_t* b) {
    asm volatile(
        "mma.sync.aligned.m16n8k16.row.col.f32.f16.f16.f32 "
        "{%0,%1,%2,%3}, {%4,%5,%6,%7}, {%8,%9}, {%0,%1,%2,%3};\n"
        : "+f"(c[0]), "+f"(c[1]), "+f"(c[2]), "+f"(c[3])
        : "r"(a[0]), "r"(a[1]), "r"(a[2]), "r"(a[3]), "r"(b[0]), "r"(b[1]));
}

__device__ __forceinline__ void cp_async16(uint32_t dst, const void* src) {
    asm volatile("cp.async.cg.shared.global [%0], [%1], 16;\n" :: "r"(dst), "l"(src));
}
__device__ __forceinline__ void cp_commit() {
    asm volatile("cp.async.commit_group;\n" ::: "memory");
}

// ---------------------------------------------------------------------------
// f32 -> f16 conversion (RN)
// ---------------------------------------------------------------------------
__global__ __launch_bounds__(256)
void f32_to_f16_kernel(const float4* __restrict__ in, uint2* __restrict__ out, int n4)
{
    int i = blockIdx.x * 256 + threadIdx.x;
    if (i < n4) {
        float4 v = in[i];
        __half2 h0 = __floats2half2_rn(v.x, v.y);
        __half2 h1 = __floats2half2_rn(v.z, v.w);
        uint2 o;
        o.x = *(uint32_t*)&h0;
        o.y = *(uint32_t*)&h1;
        out[i] = o;
    }
}

// ---------------------------------------------------------------------------
// cp.async 3-stage fp16 GEMM + BN epilogue. HOUT: write C as fp16 (half2).
// ---------------------------------------------------------------------------
#define HLD 20
#define HA_STAGE (128*HLD)
#define HB_STAGE (64*HLD)
#define HSTAGE_W (HA_STAGE + HB_STAGE)
#define GEMM_SMEM_BYTES (3*HSTAGE_W*4)

template<bool GATHER, bool HOUT>
__global__ __launch_bounds__(256)
void gemm_h_bn(const __half* __restrict__ A, const __half* __restrict__ W,
               const float* __restrict__ bn_g, const float* __restrict__ bn_b,
               const float* __restrict__ bn_m, const float* __restrict__ bn_v,
               void* __restrict__ Cv, int N)
{
    extern __shared__ uint32_t gsm[];

    const int tid  = threadIdx.x;
    const int bm   = blockIdx.y * 128;
    const int bn   = blockIdx.x * 64;
    const int warp = tid >> 5;
    const int lane = tid & 31;
    const int wm   = (warp >> 1) * 32;
    const int wn   = (warp & 1) * 32;
    const int g8   = lane >> 2;
    const int tg   = lane & 3;

    const int lrow = tid >> 2;        // 0..63
    const int seg  = tid & 3;

    int asrc[2];
#pragma unroll
    for (int j = 0; j < 2; j++) {
        int m = bm + lrow + 64 * j;
        if (GATHER) {
            int b  = m / NQTOK;
            int qq = m - b * NQTOK;
            int qi = qq / 7;
            int qj = qq - qi * 7;
            asrc[j] = b * NTOK + qi * 2 * RESOL + qj * 2;
        } else {
            asrc[j] = m;
        }
    }
    const int bsrc = bn + (lrow & 63);

    const uint32_t sbase = (uint32_t)__cvta_generic_to_shared(gsm);

    auto issue = [&](int it, int s) {
        const int k0 = it * 32;
        uint32_t abase = sbase + (uint32_t)(s * HSTAGE_W) * 4u;
#pragma unroll
        for (int j = 0; j < 2; j++) {
            uint32_t dst = abase + (uint32_t)((lrow + 64 * j) * HLD + seg * 4) * 4u;
            cp_async16(dst, A + (size_t)asrc[j] * INDIM + k0 + seg * 8);
        }
        if (lrow < 64) {
            uint32_t bbase = abase + (uint32_t)HA_STAGE * 4u;
            uint32_t dst = bbase + (uint32_t)(lrow * HLD + seg * 4) * 4u;
            cp_async16(dst, W + (size_t)bsrc * INDIM + k0 + seg * 8);
        }
        cp_commit();
    };

    float acc[2][4][4] = {};

    issue(0, 0);
    issue(1, 1);

    const int NIT = INDIM / 32;
    for (int it = 0; it < NIT; it++) {
        if (it < NIT - 1) asm volatile("cp.async.wait_group 1;\n" ::: "memory");
        else              asm volatile("cp.async.wait_group 0;\n" ::: "memory");
        __syncthreads();
        if (it + 2 < NIT) issue(it + 2, (it + 2) % 3);

        const uint32_t* As = gsm + (it % 3) * HSTAGE_W;
        const uint32_t* Bs = As + HA_STAGE;

#pragma unroll
        for (int kc = 0; kc < 2; kc++) {
            const int kb = kc * 8;
            uint32_t af[2][4];
#pragma unroll
            for (int mi = 0; mi < 2; mi++) {
                int m0 = wm + mi * 16 + g8;
                af[mi][0] = As[m0 * HLD + kb + tg];
                af[mi][1] = As[(m0 + 8) * HLD + kb + tg];
                af[mi][2] = As[m0 * HLD + kb + tg + 4];
                af[mi][3] = As[(m0 + 8) * HLD + kb + tg + 4];
            }
            uint32_t bf[4][2];
#pragma unroll
            for (int ni = 0; ni < 4; ni++) {
                int n0 = wn + ni * 8 + g8;
                bf[ni][0] = Bs[n0 * HLD + kb + tg];
                bf[ni][1] = Bs[n0 * HLD + kb + tg + 4];
            }
#pragma unroll
            for (int mi = 0; mi < 2; mi++)
#pragma unroll
                for (int ni = 0; ni < 4; ni++)
                    mma_f16(acc[mi][ni], af[mi], bf[ni]);
        }
    }

    // BN epilogue
#pragma unroll
    for (int ni = 0; ni < 4; ni++) {
        int n0 = bn + wn + ni * 8 + 2 * tg;
        float sc0 = bn_g[n0] * rsqrtf(bn_v[n0] + BN_EPS);
        float bi0 = bn_b[n0] - bn_m[n0] * sc0;
        float sc1 = bn_g[n0 + 1] * rsqrtf(bn_v[n0 + 1] + BN_EPS);
        float bi1 = bn_b[n0 + 1] - bn_m[n0 + 1] * sc1;
#pragma unroll
        for (int mi = 0; mi < 2; mi++) {
#pragma unroll
            for (int rr = 0; rr < 2; rr++) {
                int mrow = bm + wm + mi * 16 + g8 + rr * 8;
                float vx = fmaf(acc[mi][ni][rr * 2 + 0], sc0, bi0);
                float vy = fmaf(acc[mi][ni][rr * 2 + 1], sc1, bi1);
                if (HOUT) {
                    __half2 hv = __floats2half2_rn(vx, vy);
                    *(uint32_t*)((__half*)Cv + (size_t)mrow * N + n0) = *(uint32_t*)&hv;
                } else {
                    *(float2*)((float*)Cv + (size_t)mrow * N + n0) = make_float2(vx, vy);
                }
            }
        }
    }
}

// ---------------------------------------------------------------------------
// Precompute bias table
// ---------------------------------------------------------------------------
__global__ __launch_bounds__(256)
void bias_pre_kernel(const float* __restrict__ biases, const int* __restrict__ idxs,
                     float* __restrict__ tab)
{
    int i = blockIdx.x * 256 + threadIdx.x;
    if (i < NQTOK * NTOK) {
        int id = idxs[i];
#pragma unroll
        for (int h = 0; h < HEADS; h++)
            tab[(size_t)h * (NQTOK * NTOK) + i] = biases[h * NTOK + id];
    }
}

// ---------------------------------------------------------------------------
// fp16 tensor-core attention. 2 blocks per (b,h), 32 q rows each, 8 warps.
// Smem (u32):
//   Qs [32][12]   fp16 pairs along d (8 data u32)
//   Ks [200][12]  fp16 pairs along d
//   Vt [32][108]  fp16 pairs along n (104 data u32, n-pad to 208)
//   Sb [32][201]  f32 scores
//   Pb [32][108]  fp16 P pairs along n
// ---------------------------------------------------------------------------
#define QROWS 32
#define LDK 12
#define LDVT 108
#define LDP 108
#define LDS_ 201
#define QS_OFF 0
#define KS_OFF (QS_OFF + QROWS*LDK)          // 384
#define VT_OFF (KS_OFF + 200*LDK)            // 2784
#define SB_OFF (VT_OFF + 32*LDVT)            // 6240
#define PB_OFF (SB_OFF + QROWS*LDS_)         // 12672
#define ATTN_SMEM_U32 (PB_OFF + QROWS*LDP)   // 16128
#define ATTN_SMEM_BYTES (ATTN_SMEM_U32 * 4)  // 64512

__global__ __launch_bounds__(256)
void attn_h_kernel(const __half* __restrict__ kv, const __half* __restrict__ qg,
                   const float* __restrict__ btab, __half* __restrict__ ao)
{
    extern __shared__ uint32_t sm[];
    uint32_t* Qs = sm + QS_OFF;
    uint32_t* Ks = sm + KS_OFF;
    uint32_t* Vt = sm + VT_OFF;
    uint32_t* Sb = sm + SB_OFF;
    uint32_t* Pb = sm + PB_OFF;

    const int tid   = threadIdx.x;
    const int half_ = blockIdx.x & 1;
    const int bh    = blockIdx.x >> 1;
    const int b     = bh / HEADS;
    const int h     = bh - b * HEADS;
    const int qbase = half_ * QROWS;
    const int w     = tid >> 5;
    const int lane  = tid & 31;
    const int g8    = lane >> 2;
    const int tg    = lane & 3;
    const float* bt = btab + (size_t)h * (NQTOK * NTOK);

    // zero Qs + Ks pad rows
    for (int i = tid; i < QROWS * LDK; i += 256) Qs[i] = 0;
    for (int i = tid; i < 4 * LDK; i += 256) Ks[196 * LDK + i] = 0;
    __syncthreads();

    // stage Q (u32 copies of fp16 pairs)
    for (int i = tid; i < QROWS * 8; i += 256) {
        int qi = i >> 3, d2 = i & 7;
        if (qbase + qi < NQTOK)
            Qs[qi * LDK + d2] =
                ((const uint32_t*)(qg + (size_t)(b * NQTOK + qbase + qi) * KEYATTN + h * KD))[d2];
    }
    // stage K
    for (int i = tid; i < NTOK * 8; i += 256) {
        int n = i >> 3, d2 = i & 7;
        Ks[n * LDK + d2] =
            ((const uint32_t*)(kv + (size_t)(b * NTOK + n) * KVD + h * (KD + VD)))[d2];
    }
    // stage V transposed: Vt[d][p] = (V[2p][d], V[2p+1][d])
    for (int i = tid; i < 32 * 104; i += 256) {
        int d = i / 104, p = i - (i / 104) * 104;
        uint32_t v = 0;
        if (2 * p + 1 < NTOK) {
            __half lo = kv[(size_t)(b * NTOK + 2 * p) * KVD + h * (KD + VD) + KD + d];
            __half hi = kv[(size_t)(b * NTOK + 2 * p + 1) * KVD + h * (KD + VD) + KD + d];
            __half2 hv = __halves2half2(lo, hi);
            v = *(uint32_t*)&hv;
        }
        Vt[d * LDVT + p] = v;
    }
    __syncthreads();

    // ---- S = Q K^T * SCALE + bias ----  (one m16n8k16 per n-tile)
    {
        const int mt = w >> 2;
        const int nq = w & 3;
        const int nt0 = (nq == 0) ? 0 : (nq == 1) ? 6 : (nq == 2) ? 12 : 18;
        const int nt1 = (nq == 0) ? 6 : (nq == 1) ? 12 : (nq == 2) ? 18 : 25;

        const int r = mt * 16 + g8;
        uint32_t a[4];
        a[0] = Qs[r * LDK + tg];
        a[1] = Qs[(r + 8) * LDK + tg];
        a[2] = Qs[r * LDK + tg + 4];
        a[3] = Qs[(r + 8) * LDK + tg + 4];

        for (int nt = nt0; nt < nt1; nt++) {
            float c[4] = {0.f, 0.f, 0.f, 0.f};
            uint32_t bfr[2];
            bfr[0] = Ks[(nt * 8 + g8) * LDK + tg];
            bfr[1] = Ks[(nt * 8 + g8) * LDK + tg + 4];
            mma_f16(c, a, bfr);

            int r0 = mt * 16 + g8;
            int r1 = r0 + 8;
            int gq0 = qbase + r0;
            int gq1 = qbase + r1;
            int col = nt * 8 + 2 * tg;
            float2 bv0 = make_float2(0.f, 0.f), bv1 = make_float2(0.f, 0.f);
            if (col < NTOK) {
                if (gq0 < NQTOK) bv0 = *(const float2*)(bt + gq0 * NTOK + col);
                if (gq1 < NQTOK) bv1 = *(const float2*)(bt + gq1 * NTOK + col);
            }
            Sb[r0 * LDS_ + col]     = __float_as_uint(fmaf(c[0], ATTNSCALE, bv0.x));
            Sb[r0 * LDS_ + col + 1] = __float_as_uint(fmaf(c[1], ATTNSCALE, bv0.y));
            Sb[r1 * LDS_ + col]     = __float_as_uint(fmaf(c[2], ATTNSCALE, bv1.x));
            Sb[r1 * LDS_ + col + 1] = __float_as_uint(fmaf(c[3], ATTNSCALE, bv1.y));
        }
    }
    __syncthreads();

    // ---- softmax rows (warp per row), pack P as fp16 pairs ----
    for (int r = w; r < QROWS; r += 8) {
        float s0[4], s1[4];
        float mx = -1e30f;
#pragma unroll
        for (int it = 0; it < 4; it++) {
            int p = lane + it * 32;
            if (p < 98) {
                s0[it] = __uint_as_float(Sb[r * LDS_ + 2 * p]);
                s1[it] = __uint_as_float(Sb[r * LDS_ + 2 * p + 1]);
                mx = fmaxf(mx, fmaxf(s0[it], s1[it]));
            } else {
                s0[it] = -1e30f; s1[it] = -1e30f;
            }
        }
#pragma unroll
        for (int o = 16; o > 0; o >>= 1)
            mx = fmaxf(mx, __shfl_xor_sync(0xffffffffu, mx, o));
        float sum = 0.f;
        float e0[4], e1[4];
#pragma unroll
        for (int it = 0; it < 4; it++) {
            int p = lane + it * 32;
            if (p < 98) {
                e0[it] = __expf(s0[it] - mx);
                e1[it] = __expf(s1[it] - mx);
                sum += e0[it] + e1[it];
            } else { e0[it] = 0.f; e1[it] = 0.f; }
        }
#pragma unroll
        for (int o = 16; o > 0; o >>= 1)
            sum += __shfl_xor_sync(0xffffffffu, sum, o);
        float inv = 1.f / sum;
#pragma unroll
        for (int it = 0; it < 4; it++) {
            int p = lane + it * 32;
            if (p < 104) {
                __half2 hv = __floats2half2_rn(e0[it] * inv, e1[it] * inv);
                Pb[r * LDP + p] = *(uint32_t*)&hv;
            }
        }
    }
    __syncthreads();

    // ---- O = P V, silu, fp16 store ----  (13 k-steps of 16)
    {
        const int mt = w >> 2;
        const int dh = w & 3;
        const int r = mt * 16 + g8;
        float acc[4] = {0.f, 0.f, 0.f, 0.f};
#pragma unroll
        for (int ks = 0; ks < 13; ks++) {
            int ku = ks * 8;
            uint32_t a[4];
            a[0] = Pb[r * LDP + ku + tg];
            a[1] = Pb[(r + 8) * LDP + ku + tg];
            a[2] = Pb[r * LDP + ku + tg + 4];
            a[3] = Pb[(r + 8) * LDP + ku + tg + 4];
            uint32_t bfr[2];
            bfr[0] = Vt[(dh * 8 + g8) * LDVT + ku + tg];
            bfr[1] = Vt[(dh * 8 + g8) * LDVT + ku + tg + 4];
            mma_f16(acc, a, bfr);
        }
        int d0  = dh * 8 + 2 * tg;
        int gq0 = qbase + mt * 16 + g8;
        int gq1 = gq0 + 8;
        if (gq0 < NQTOK) {
            float o0 = acc[0], o1 = acc[1];
            __half2 v = __floats2half2_rn(o0 / (1.f + __expf(-o0)),
                                          o1 / (1.f + __expf(-o1)));
            *(uint32_t*)(ao + (size_t)(b * NQTOK + gq0) * VALATTN + h * VD + d0) =
                *(uint32_t*)&v;
        }
        if (gq1 < NQTOK) {
            float o0 = acc[2], o1 = acc[3];
            __half2 v = __floats2half2_rn(o0 / (1.f + __expf(-o0)),
                                          o1 / (1.f + __expf(-o1)));
            *(uint32_t*)(ao + (size_t)(b * NQTOK + gq1) * VALATTN + h * VD + d0) =
                *(uint32_t*)&v;
        }
    }
}

// ---------------------------------------------------------------------------
// Launch
// ---------------------------------------------------------------------------
extern "C" void kernel_launch(void* const* d_in, const int* in_sizes, int n_in,
                              void* d_out, int out_size)
{
    const float* x     = (const float*)d_in[0];
    const float* kv_w  = (const float*)d_in[1];
    const float* kv_g  = (const float*)d_in[2];
    const float* kv_b  = (const float*)d_in[3];
    const float* kv_m  = (const float*)d_in[4];
    const float* kv_v  = (const float*)d_in[5];
    const float* q_w   = (const float*)d_in[6];
    const float* q_g   = (const float*)d_in[7];
    const float* q_b   = (const float*)d_in[8];
    const float* q_m   = (const float*)d_in[9];
    const float* q_v   = (const float*)d_in[10];
    const float* pj_w  = (const float*)d_in[11];
    const float* pj_g  = (const float*)d_in[12];
    const float* pj_b  = (const float*)d_in[13];
    const float* pj_m  = (const float*)d_in[14];
    const float* pj_v  = (const float*)d_in[15];
    const float* biases    = (const float*)d_in[16];
    const int*   bias_idxs = (const int*)d_in[17];
    float* out = (float*)d_out;

    float  *btab;
    __half *kvh, *qh, *aoh, *xh, *wh;
    cudaGetSymbolAddress((void**)&kvh,  g_kvh);
    cudaGetSymbolAddress((void**)&qh,   g_qh);
    cudaGetSymbolAddress((void**)&aoh,  g_aoh);
    cudaGetSymbolAddress((void**)&btab, g_btab);
    cudaGetSymbolAddress((void**)&xh,   g_xh);
    cudaGetSymbolAddress((void**)&wh,   g_wh);

    cudaFuncSetAttribute(attn_h_kernel,
                         cudaFuncAttributeMaxDynamicSharedMemorySize, ATTN_SMEM_BYTES);
    cudaFuncSetAttribute(gemm_h_bn<false, true>,
                         cudaFuncAttributeMaxDynamicSharedMemorySize, GEMM_SMEM_BYTES);
    cudaFuncSetAttribute(gemm_h_bn<true, true>,
                         cudaFuncAttributeMaxDynamicSharedMemorySize, GEMM_SMEM_BYTES);
    cudaFuncSetAttribute(gemm_h_bn<false, false>,
                         cudaFuncAttributeMaxDynamicSharedMemorySize, GEMM_SMEM_BYTES);

    // Convert x and weights to fp16
    {
        int n4 = (M1 * INDIM) / 4;
        f32_to_f16_kernel<<<(n4 + 255) / 256, 256>>>((const float4*)x, (uint2*)xh, n4);
        int nkv = (KVD * INDIM) / 4;
        f32_to_f16_kernel<<<(nkv + 255) / 256, 256>>>((const float4*)kv_w, (uint2*)(wh + WR_KV), nkv);
        int nq = (KEYATTN * INDIM) / 4;
        f32_to_f16_kernel<<<(nq + 255) / 256, 256>>>((const float4*)q_w, (uint2*)(wh + WR_Q), nq);
        int npj = (OUTDIM * INDIM) / 4;
        f32_to_f16_kernel<<<(npj + 255) / 256, 256>>>((const float4*)pj_w, (uint2*)(wh + WR_PJ), npj);
    }

    bias_pre_kernel<<<(NQTOK * NTOK + 255) / 256, 256>>>(biases, bias_idxs, btab);

    // GEMM1: kv = BN(x @ kv_w^T)   [50176 x 576] -> fp16
    gemm_h_bn<false, true><<<dim3(KVD / 64, M1 / 128), 256, GEMM_SMEM_BYTES>>>(
        xh, wh + WR_KV, kv_g, kv_b, kv_m, kv_v, kvh, KVD);

    // GEMM2: q = BN(xq @ q_w^T)    [12544 x 192] -> fp16, gathered rows
    gemm_h_bn<true, true><<<dim3(KEYATTN / 64, M2 / 128), 256, GEMM_SMEM_BYTES>>>(
        xh, wh + WR_Q, q_g, q_b, q_m, q_v, qh, KEYATTN);

    // Attention (fp16 mma), writes fp16
    attn_h_kernel<<<BATCH * HEADS * 2, 256, ATTN_SMEM_BYTES>>>(
        kvh, qh, btab, aoh);

    // GEMM3: out = BN(silu_attn @ pj_w^T)  [12544 x 512] -> f32
    gemm_h_bn<false, false><<<dim3(OUTDIM / 64, M2 / 128), 256, GEMM_SMEM_BYTES>>>(
        aoh, wh + WR_PJ, pj_g, pj_b, pj_m, pj_v, out, OUTDIM);
}

// round 13
// speedup vs baseline: 1.2700x; 1.2700x over previous
#include <cuda_runtime.h>
#include <cuda_fp16.h>
#include <math.h>
#include <stdint.h>

// ---------------------------------------------------------------------------
// Problem constants
// ---------------------------------------------------------------------------
#define BATCH    256
#define RESOL    14
#define NTOK     196
#define NQTOK    49
#define INDIM    384
#define HEADS    12
#define KD       16
#define VD       32
#define KVD      576
#define KEYATTN  192
#define VALATTN  384
#define OUTDIM   512
#define ATTNSCALE 0.25f
#define BN_EPS   1e-5f

#define M1 (BATCH*NTOK)   // 50176
#define M2 (BATCH*NQTOK)  // 12544

#define WR_KV 0
#define WR_Q  (576*INDIM)
#define WR_PJ (768*INDIM)

// Scratch (device globals)
__device__ __half g_kvh[(size_t)M1 * KVD];
__device__ __half g_qh [(size_t)M2 * KEYATTN];
__device__ __half g_aoh[(size_t)M2 * VALATTN];
__device__ float  g_btab[(size_t)HEADS * NQTOK * NTOK];
__device__ __half g_xh [(size_t)M1 * INDIM];
__device__ __half g_wh [(size_t)1280 * INDIM];

// ---------------------------------------------------------------------------
// helpers
// ---------------------------------------------------------------------------
__device__ __forceinline__ void mma_f16(float* c, const uint32_t* a, const uint32_t* b) {
    asm volatile(
        "mma.sync.aligned.m16n8k16.row.col.f32.f16.f16.f32 "
        "{%0,%1,%2,%3}, {%4,%5,%6,%7}, {%8,%9}, {%0,%1,%2,%3};\n"
        : "+f"(c[0]), "+f"(c[1]), "+f"(c[2]), "+f"(c[3])
        : "r"(a[0]), "r"(a[1]), "r"(a[2]), "r"(a[3]), "r"(b[0]), "r"(b[1]));
}

__device__ __forceinline__ void cp_async16(uint32_t dst, const void* src) {
    asm volatile("cp.async.cg.shared.global [%0], [%1], 16;\n" :: "r"(dst), "l"(src));
}
__device__ __forceinline__ void cp_commit() {
    asm volatile("cp.async.commit_group;\n" ::: "memory");
}

// ---------------------------------------------------------------------------
// Merged f32 -> f16 conversion (x + 3 weights), one launch
// ---------------------------------------------------------------------------
#define N4_X   ((M1*INDIM)/4)
#define N4_KV  ((KVD*INDIM)/4)
#define N4_Q   ((KEYATTN*INDIM)/4)
#define N4_PJ  ((OUTDIM*INDIM)/4)
#define N4_ALL (N4_X + N4_KV + N4_Q + N4_PJ)

__global__ __launch_bounds__(256)
void conv_all_kernel(const float4* __restrict__ x,  const float4* __restrict__ kvw,
                     const float4* __restrict__ qw, const float4* __restrict__ pjw,
                     uint2* __restrict__ xh, uint2* __restrict__ wh)
{
    int i = blockIdx.x * 256 + threadIdx.x;
    if (i >= N4_ALL) return;
    const float4* src;
    uint2* dst;
    int j = i;
    if (j < N4_X)                    { src = x;   dst = xh;                 }
    else if ((j -= N4_X) < N4_KV)    { src = kvw; dst = wh + WR_KV/4;       }
    else if ((j -= N4_KV) < N4_Q)    { src = qw;  dst = wh + WR_Q/4;        }
    else { j -= N4_Q;                  src = pjw; dst = wh + WR_PJ/4;       }
    float4 v = src[j];
    __half2 h0 = __floats2half2_rn(v.x, v.y);
    __half2 h1 = __floats2half2_rn(v.z, v.w);
    uint2 o;
    o.x = *(uint32_t*)&h0;
    o.y = *(uint32_t*)&h1;
    dst[j] = o;
}

// ---------------------------------------------------------------------------
// cp.async 3-stage fp16 GEMM + BN epilogue. HOUT: write C as fp16 (half2).
// ---------------------------------------------------------------------------
#define HLD 20
#define HA_STAGE (128*HLD)
#define HB_STAGE (64*HLD)
#define HSTAGE_W (HA_STAGE + HB_STAGE)
#define GEMM_SMEM_BYTES (3*HSTAGE_W*4)

template<bool GATHER, bool HOUT>
__global__ __launch_bounds__(256)
void gemm_h_bn(const __half* __restrict__ A, const __half* __restrict__ W,
               const float* __restrict__ bn_g, const float* __restrict__ bn_b,
               const float* __restrict__ bn_m, const float* __restrict__ bn_v,
               void* __restrict__ Cv, int N)
{
    extern __shared__ uint32_t gsm[];

    const int tid  = threadIdx.x;
    const int bm   = blockIdx.y * 128;
    const int bn   = blockIdx.x * 64;
    const int warp = tid >> 5;
    const int lane = tid & 31;
    const int wm   = (warp >> 1) * 32;
    const int wn   = (warp & 1) * 32;
    const int g8   = lane >> 2;
    const int tg   = lane & 3;

    const int lrow = tid >> 2;
    const int seg  = tid & 3;

    int asrc[2];
#pragma unroll
    for (int j = 0; j < 2; j++) {
        int m = bm + lrow + 64 * j;
        if (GATHER) {
            int b  = m / NQTOK;
            int qq = m - b * NQTOK;
            int qi = qq / 7;
            int qj = qq - qi * 7;
            asrc[j] = b * NTOK + qi * 2 * RESOL + qj * 2;
        } else {
            asrc[j] = m;
        }
    }
    const int bsrc = bn + (lrow & 63);

    const uint32_t sbase = (uint32_t)__cvta_generic_to_shared(gsm);

    auto issue = [&](int it, int s) {
        const int k0 = it * 32;
        uint32_t abase = sbase + (uint32_t)(s * HSTAGE_W) * 4u;
#pragma unroll
        for (int j = 0; j < 2; j++) {
            uint32_t dst = abase + (uint32_t)((lrow + 64 * j) * HLD + seg * 4) * 4u;
            cp_async16(dst, A + (size_t)asrc[j] * INDIM + k0 + seg * 8);
        }
        if (lrow < 64) {
            uint32_t bbase = abase + (uint32_t)HA_STAGE * 4u;
            uint32_t dst = bbase + (uint32_t)(lrow * HLD + seg * 4) * 4u;
            cp_async16(dst, W + (size_t)bsrc * INDIM + k0 + seg * 8);
        }
        cp_commit();
    };

    float acc[2][4][4] = {};

    issue(0, 0);
    issue(1, 1);

    const int NIT = INDIM / 32;
    for (int it = 0; it < NIT; it++) {
        if (it < NIT - 1) asm volatile("cp.async.wait_group 1;\n" ::: "memory");
        else              asm volatile("cp.async.wait_group 0;\n" ::: "memory");
        __syncthreads();
        if (it + 2 < NIT) issue(it + 2, (it + 2) % 3);

        const uint32_t* As = gsm + (it % 3) * HSTAGE_W;
        const uint32_t* Bs = As + HA_STAGE;

#pragma unroll
        for (int kc = 0; kc < 2; kc++) {
            const int kb = kc * 8;
            uint32_t af[2][4];
#pragma unroll
            for (int mi = 0; mi < 2; mi++) {
                int m0 = wm + mi * 16 + g8;
                af[mi][0] = As[m0 * HLD + kb + tg];
                af[mi][1] = As[(m0 + 8) * HLD + kb + tg];
                af[mi][2] = As[m0 * HLD + kb + tg + 4];
                af[mi][3] = As[(m0 + 8) * HLD + kb + tg + 4];
            }
            uint32_t bf[4][2];
#pragma unroll
            for (int ni = 0; ni < 4; ni++) {
                int n0 = wn + ni * 8 + g8;
                bf[ni][0] = Bs[n0 * HLD + kb + tg];
                bf[ni][1] = Bs[n0 * HLD + kb + tg + 4];
            }
#pragma unroll
            for (int mi = 0; mi < 2; mi++)
#pragma unroll
                for (int ni = 0; ni < 4; ni++)
                    mma_f16(acc[mi][ni], af[mi], bf[ni]);
        }
    }

    // BN epilogue
#pragma unroll
    for (int ni = 0; ni < 4; ni++) {
        int n0 = bn + wn + ni * 8 + 2 * tg;
        float sc0 = bn_g[n0] * rsqrtf(bn_v[n0] + BN_EPS);
        float bi0 = bn_b[n0] - bn_m[n0] * sc0;
        float sc1 = bn_g[n0 + 1] * rsqrtf(bn_v[n0 + 1] + BN_EPS);
        float bi1 = bn_b[n0 + 1] - bn_m[n0 + 1] * sc1;
#pragma unroll
        for (int mi = 0; mi < 2; mi++) {
#pragma unroll
            for (int rr = 0; rr < 2; rr++) {
                int mrow = bm + wm + mi * 16 + g8 + rr * 8;
                float vx = fmaf(acc[mi][ni][rr * 2 + 0], sc0, bi0);
                float vy = fmaf(acc[mi][ni][rr * 2 + 1], sc1, bi1);
                if (HOUT) {
                    __half2 hv = __floats2half2_rn(vx, vy);
                    *(uint32_t*)((__half*)Cv + (size_t)mrow * N + n0) = *(uint32_t*)&hv;
                } else {
                    *(float2*)((float*)Cv + (size_t)mrow * N + n0) = make_float2(vx, vy);
                }
            }
        }
    }
}

// ---------------------------------------------------------------------------
// Precompute bias table
// ---------------------------------------------------------------------------
__global__ __launch_bounds__(256)
void bias_pre_kernel(const float* __restrict__ biases, const int* __restrict__ idxs,
                     float* __restrict__ tab)
{
    int i = blockIdx.x * 256 + threadIdx.x;
    if (i < NQTOK * NTOK) {
        int id = idxs[i];
#pragma unroll
        for (int h = 0; h < HEADS; h++)
            tab[(size_t)h * (NQTOK * NTOK) + i] = biases[h * NTOK + id];
    }
}

// ---------------------------------------------------------------------------
// fp16 tensor-core attention. 2 blocks per (b,h), 32 q rows each, 8 warps.
// V staged coalesced into Vn (aliased over Sb), then transposed in smem.
// ---------------------------------------------------------------------------
#define QROWS 32
#define LDK 12
#define LDVT 108
#define LDP 108
#define LDS_ 201
#define LDVN 17
#define QS_OFF 0
#define KS_OFF (QS_OFF + QROWS*LDK)          // 384
#define VT_OFF (KS_OFF + 200*LDK)            // 2784
#define SB_OFF (VT_OFF + 32*LDVT)            // 6240
#define PB_OFF (SB_OFF + QROWS*LDS_)         // 12672
#define ATTN_SMEM_U32 (PB_OFF + QROWS*LDP)   // 16128
#define ATTN_SMEM_BYTES (ATTN_SMEM_U32 * 4)  // 64512

__global__ __launch_bounds__(256)
void attn_h_kernel(const __half* __restrict__ kv, const __half* __restrict__ qg,
                   const float* __restrict__ btab, __half* __restrict__ ao)
{
    extern __shared__ uint32_t sm[];
    uint32_t* Qs = sm + QS_OFF;
    uint32_t* Ks = sm + KS_OFF;
    uint32_t* Vt = sm + VT_OFF;
    uint32_t* Sb = sm + SB_OFF;
    uint32_t* Pb = sm + PB_OFF;
    uint32_t* Vn = Sb;                        // scratch alias (196*17 <= 32*201)

    const int tid   = threadIdx.x;
    const int half_ = blockIdx.x & 1;
    const int bh    = blockIdx.x >> 1;
    const int b     = bh / HEADS;
    const int h     = bh - b * HEADS;
    const int qbase = half_ * QROWS;
    const int w     = tid >> 5;
    const int lane  = tid & 31;
    const int g8    = lane >> 2;
    const int tg    = lane & 3;
    const float* bt = btab + (size_t)h * (NQTOK * NTOK);

    // zero Qs + Ks pad rows
    for (int i = tid; i < QROWS * LDK; i += 256) Qs[i] = 0;
    for (int i = tid; i < 4 * LDK; i += 256) Ks[196 * LDK + i] = 0;
    __syncthreads();   // zero-fill must complete before staging (race fix)

    // stage Q (u32 copies of fp16 pairs)
    for (int i = tid; i < QROWS * 8; i += 256) {
        int qi = i >> 3, d2 = i & 7;
        if (qbase + qi < NQTOK)
            Qs[qi * LDK + d2] =
                ((const uint32_t*)(qg + (size_t)(b * NQTOK + qbase + qi) * KEYATTN + h * KD))[d2];
    }
    // stage K (coalesced u32)
    for (int i = tid; i < NTOK * 8; i += 256) {
        int n = i >> 3, d2 = i & 7;
        Ks[n * LDK + d2] =
            ((const uint32_t*)(kv + (size_t)(b * NTOK + n) * KVD + h * (KD + VD)))[d2];
    }
    // stage V rows coalesced into Vn [n][16 u32]
    for (int i = tid; i < NTOK * 16; i += 256) {
        int n = i >> 4, d2 = i & 15;
        Vn[n * LDVN + d2] =
            ((const uint32_t*)(kv + (size_t)(b * NTOK + n) * KVD + h * (KD + VD) + KD))[d2];
    }
    __syncthreads();

    // transpose in smem: Vt[d][p] = (V[2p][d], V[2p+1][d])
    {
        const __half* Vnh = (const __half*)Vn;
        for (int i = tid; i < 32 * 104; i += 256) {
            int d = i / 104, p = i - (i / 104) * 104;
            uint32_t v = 0;
            if (2 * p + 1 < NTOK) {
                __half2 hv = __halves2half2(Vnh[(2 * p) * (2 * LDVN) + d],
                                            Vnh[(2 * p + 1) * (2 * LDVN) + d]);
                v = *(uint32_t*)&hv;
            }
            Vt[d * LDVT + p] = v;
        }
    }
    __syncthreads();

    // ---- S = Q K^T * SCALE + bias ----  (one m16n8k16 per n-tile)
    {
        const int mt = w >> 2;
        const int nq = w & 3;
        const int nt0 = (nq == 0) ? 0 : (nq == 1) ? 6 : (nq == 2) ? 12 : 18;
        const int nt1 = (nq == 0) ? 6 : (nq == 1) ? 12 : (nq == 2) ? 18 : 25;

        const int r = mt * 16 + g8;
        uint32_t a[4];
        a[0] = Qs[r * LDK + tg];
        a[1] = Qs[(r + 8) * LDK + tg];
        a[2] = Qs[r * LDK + tg + 4];
        a[3] = Qs[(r + 8) * LDK + tg + 4];

        for (int nt = nt0; nt < nt1; nt++) {
            float c[4] = {0.f, 0.f, 0.f, 0.f};
            uint32_t bfr[2];
            bfr[0] = Ks[(nt * 8 + g8) * LDK + tg];
            bfr[1] = Ks[(nt * 8 + g8) * LDK + tg + 4];
            mma_f16(c, a, bfr);

            int r0 = mt * 16 + g8;
            int r1 = r0 + 8;
            int gq0 = qbase + r0;
            int gq1 = qbase + r1;
            int col = nt * 8 + 2 * tg;
            float2 bv0 = make_float2(0.f, 0.f), bv1 = make_float2(0.f, 0.f);
            if (col < NTOK) {
                if (gq0 < NQTOK) bv0 = *(const float2*)(bt + gq0 * NTOK + col);
                if (gq1 < NQTOK) bv1 = *(const float2*)(bt + gq1 * NTOK + col);
            }
            Sb[r0 * LDS_ + col]     = __float_as_uint(fmaf(c[0], ATTNSCALE, bv0.x));
            Sb[r0 * LDS_ + col + 1] = __float_as_uint(fmaf(c[1], ATTNSCALE, bv0.y));
            Sb[r1 * LDS_ + col]     = __float_as_uint(fmaf(c[2], ATTNSCALE, bv1.x));
            Sb[r1 * LDS_ + col + 1] = __float_as_uint(fmaf(c[3], ATTNSCALE, bv1.y));
        }
    }
    __syncthreads();

    // ---- softmax rows (warp per row), pack P as fp16 pairs ----
    for (int r = w; r < QROWS; r += 8) {
        float s0[4], s1[4];
        float mx = -1e30f;
#pragma unroll
        for (int it = 0; it < 4; it++) {
            int p = lane + it * 32;
            if (p < 98) {
                s0[it] = __uint_as_float(Sb[r * LDS_ + 2 * p]);
                s1[it] = __uint_as_float(Sb[r * LDS_ + 2 * p + 1]);
                mx = fmaxf(mx, fmaxf(s0[it], s1[it]));
            } else {
                s0[it] = -1e30f; s1[it] = -1e30f;
            }
        }
#pragma unroll
        for (int o = 16; o > 0; o >>= 1)
            mx = fmaxf(mx, __shfl_xor_sync(0xffffffffu, mx, o));
        float sum = 0.f;
        float e0[4], e1[4];
#pragma unroll
        for (int it = 0; it < 4; it++) {
            int p = lane + it * 32;
            if (p < 98) {
                e0[it] = __expf(s0[it] - mx);
                e1[it] = __expf(s1[it] - mx);
                sum += e0[it] + e1[it];
            } else { e0[it] = 0.f; e1[it] = 0.f; }
        }
#pragma unroll
        for (int o = 16; o > 0; o >>= 1)
            sum += __shfl_xor_sync(0xffffffffu, sum, o);
        float inv = 1.f / sum;
#pragma unroll
        for (int it = 0; it < 4; it++) {
            int p = lane + it * 32;
            if (p < 104) {
                __half2 hv = __floats2half2_rn(e0[it] * inv, e1[it] * inv);
                Pb[r * LDP + p] = *(uint32_t*)&hv;
            }
        }
    }
    __syncthreads();

    // ---- O = P V, silu, fp16 store ----  (13 k-steps of 16)
    {
        const int mt = w >> 2;
        const int dh = w & 3;
        const int r = mt * 16 + g8;
        float acc[4] = {0.f, 0.f, 0.f, 0.f};
#pragma unroll
        for (int ks = 0; ks < 13; ks++) {
            int ku = ks * 8;
            uint32_t a[4];
            a[0] = Pb[r * LDP + ku + tg];
            a[1] = Pb[(r + 8) * LDP + ku + tg];
            a[2] = Pb[r * LDP + ku + tg + 4];
            a[3] = Pb[(r + 8) * LDP + ku + tg + 4];
            uint32_t bfr[2];
            bfr[0] = Vt[(dh * 8 + g8) * LDVT + ku + tg];
            bfr[1] = Vt[(dh * 8 + g8) * LDVT + ku + tg + 4];
            mma_f16(acc, a, bfr);
        }
        int d0  = dh * 8 + 2 * tg;
        int gq0 = qbase + mt * 16 + g8;
        int gq1 = gq0 + 8;
        if (gq0 < NQTOK) {
            float o0 = acc[0], o1 = acc[1];
            __half2 v = __floats2half2_rn(o0 / (1.f + __expf(-o0)),
                                          o1 / (1.f + __expf(-o1)));
            *(uint32_t*)(ao + (size_t)(b * NQTOK + gq0) * VALATTN + h * VD + d0) =
                *(uint32_t*)&v;
        }
        if (gq1 < NQTOK) {
            float o0 = acc[2], o1 = acc[3];
            __half2 v = __floats2half2_rn(o0 / (1.f + __expf(-o0)),
                                          o1 / (1.f + __expf(-o1)));
            *(uint32_t*)(ao + (size_t)(b * NQTOK + gq1) * VALATTN + h * VD + d0) =
                *(uint32_t*)&v;
        }
    }
}

// ---------------------------------------------------------------------------
// Launch
// ---------------------------------------------------------------------------
extern "C" void kernel_launch(void* const* d_in, const int* in_sizes, int n_in,
                              void* d_out, int out_size)
{
    const float* x     = (const float*)d_in[0];
    const float* kv_w  = (const float*)d_in[1];
    const float* kv_g  = (const float*)d_in[2];
    const float* kv_b  = (const float*)d_in[3];
    const float* kv_m  = (const float*)d_in[4];
    const float* kv_v  = (const float*)d_in[5];
    const float* q_w   = (const float*)d_in[6];
    const float* q_g   = (const float*)d_in[7];
    const float* q_b   = (const float*)d_in[8];
    const float* q_m   = (const float*)d_in[9];
    const float* q_v   = (const float*)d_in[10];
    const float* pj_w  = (const float*)d_in[11];
    const float* pj_g  = (const float*)d_in[12];
    const float* pj_b  = (const float*)d_in[13];
    const float* pj_m  = (const float*)d_in[14];
    const float* pj_v  = (const float*)d_in[15];
    const float* biases    = (const float*)d_in[16];
    const int*   bias_idxs = (const int*)d_in[17];
    float* out = (float*)d_out;

    float  *btab;
    __half *kvh, *qh, *aoh, *xh, *wh;
    cudaGetSymbolAddress((void**)&kvh,  g_kvh);
    cudaGetSymbolAddress((void**)&qh,   g_qh);
    cudaGetSymbolAddress((void**)&aoh,  g_aoh);
    cudaGetSymbolAddress((void**)&btab, g_btab);
    cudaGetSymbolAddress((void**)&xh,   g_xh);
    cudaGetSymbolAddress((void**)&wh,   g_wh);

    cudaFuncSetAttribute(attn_h_kernel,
                         cudaFuncAttributeMaxDynamicSharedMemorySize, ATTN_SMEM_BYTES);
    cudaFuncSetAttribute(gemm_h_bn<false, true>,
                         cudaFuncAttributeMaxDynamicSharedMemorySize, GEMM_SMEM_BYTES);
    cudaFuncSetAttribute(gemm_h_bn<true, true>,
                         cudaFuncAttributeMaxDynamicSharedMemorySize, GEMM_SMEM_BYTES);
    cudaFuncSetAttribute(gemm_h_bn<false, false>,
                         cudaFuncAttributeMaxDynamicSharedMemorySize, GEMM_SMEM_BYTES);

    // One merged conversion launch
    conv_all_kernel<<<(N4_ALL + 255) / 256, 256>>>(
        (const float4*)x, (const float4*)kv_w, (const float4*)q_w, (const float4*)pj_w,
        (uint2*)xh, (uint2*)wh);

    bias_pre_kernel<<<(NQTOK * NTOK + 255) / 256, 256>>>(biases, bias_idxs, btab);

    // GEMM1: kv = BN(x @ kv_w^T)   [50176 x 576] -> fp16
    gemm_h_bn<false, true><<<dim3(KVD / 64, M1 / 128), 256, GEMM_SMEM_BYTES>>>(
        xh, wh + WR_KV, kv_g, kv_b, kv_m, kv_v, kvh, KVD);

    // GEMM2: q = BN(xq @ q_w^T)    [12544 x 192] -> fp16, gathered rows
    gemm_h_bn<true, true><<<dim3(KEYATTN / 64, M2 / 128), 256, GEMM_SMEM_BYTES>>>(
        xh, wh + WR_Q, q_g, q_b, q_m, q_v, qh, KEYATTN);

    // Attention (fp16 mma), writes fp16
    attn_h_kernel<<<BATCH * HEADS * 2, 256, ATTN_SMEM_BYTES>>>(
        kvh, qh, btab, aoh);

    // GEMM3: out = BN(silu_attn @ pj_w^T)  [12544 x 512] -> f32
    gemm_h_bn<false, false><<<dim3(OUTDIM / 64, M2 / 128), 256, GEMM_SMEM_BYTES>>>(
        aoh, wh + WR_PJ, pj_g, pj_b, pj_m, pj_v, out, OUTDIM);
}

// round 14
// speedup vs baseline: 1.2917x; 1.0171x over previous
#include <cuda_runtime.h>
#include <cuda_fp16.h>
#include <math.h>
#include <stdint.h>

// ---------------------------------------------------------------------------
// Problem constants
// ---------------------------------------------------------------------------
#define BATCH    256
#define RESOL    14
#define NTOK     196
#define NQTOK    49
#define INDIM    384
#define HEADS    12
#define KD       16
#define VD       32
#define KVD      576
#define KEYATTN  192
#define VALATTN  384
#define OUTDIM   512
#define ATTNSCALE 0.25f
#define BN_EPS   1e-5f

#define M1 (BATCH*NTOK)   // 50176
#define M2 (BATCH*NQTOK)  // 12544

#define WR_KV 0
#define WR_Q  (576*INDIM)
#define WR_PJ (768*INDIM)

// Scratch (device globals)
__device__ __half g_kvh[(size_t)M1 * KVD];
__device__ __half g_qh [(size_t)M2 * KEYATTN];
__device__ __half g_aoh[(size_t)M2 * VALATTN];
__device__ float  g_btab[(size_t)HEADS * NQTOK * NTOK];
__device__ __half g_xh [(size_t)M1 * INDIM];
__device__ __half g_wh [(size_t)1280 * INDIM];

// ---------------------------------------------------------------------------
// helpers
// ---------------------------------------------------------------------------
__device__ __forceinline__ void mma_f16(float* c, const uint32_t* a, const uint32_t* b) {
    asm volatile(
        "mma.sync.aligned.m16n8k16.row.col.f32.f16.f16.f32 "
        "{%0,%1,%2,%3}, {%4,%5,%6,%7}, {%8,%9}, {%0,%1,%2,%3};\n"
        : "+f"(c[0]), "+f"(c[1]), "+f"(c[2]), "+f"(c[3])
        : "r"(a[0]), "r"(a[1]), "r"(a[2]), "r"(a[3]), "r"(b[0]), "r"(b[1]));
}

__device__ __forceinline__ void ldmatrix_x4(uint32_t* r, uint32_t addr) {
    asm volatile("ldmatrix.sync.aligned.m8n8.x4.shared.b16 {%0,%1,%2,%3}, [%4];"
                 : "=r"(r[0]), "=r"(r[1]), "=r"(r[2]), "=r"(r[3]) : "r"(addr));
}

__device__ __forceinline__ void cp_async16(uint32_t dst, const void* src) {
    asm volatile("cp.async.cg.shared.global [%0], [%1], 16;\n" :: "r"(dst), "l"(src));
}
__device__ __forceinline__ void cp_commit() {
    asm volatile("cp.async.commit_group;\n" ::: "memory");
}

// ---------------------------------------------------------------------------
// Merged f32 -> f16 conversion (x + 3 weights), one launch
// ---------------------------------------------------------------------------
#define N4_X   ((M1*INDIM)/4)
#define N4_KV  ((KVD*INDIM)/4)
#define N4_Q   ((KEYATTN*INDIM)/4)
#define N4_PJ  ((OUTDIM*INDIM)/4)
#define N4_ALL (N4_X + N4_KV + N4_Q + N4_PJ)

__global__ __launch_bounds__(256)
void conv_all_kernel(const float4* __restrict__ x,  const float4* __restrict__ kvw,
                     const float4* __restrict__ qw, const float4* __restrict__ pjw,
                     uint2* __restrict__ xh, uint2* __restrict__ wh)
{
    int i = blockIdx.x * 256 + threadIdx.x;
    if (i >= N4_ALL) return;
    const float4* src;
    uint2* dst;
    int j = i;
    if (j < N4_X)                    { src = x;   dst = xh;                 }
    else if ((j -= N4_X) < N4_KV)    { src = kvw; dst = wh + WR_KV/4;       }
    else if ((j -= N4_KV) < N4_Q)    { src = qw;  dst = wh + WR_Q/4;        }
    else { j -= N4_Q;                  src = pjw; dst = wh + WR_PJ/4;       }
    float4 v = src[j];
    __half2 h0 = __floats2half2_rn(v.x, v.y);
    __half2 h1 = __floats2half2_rn(v.z, v.w);
    uint2 o;
    o.x = *(uint32_t*)&h0;
    o.y = *(uint32_t*)&h1;
    dst[j] = o;
}

// ---------------------------------------------------------------------------
// cp.async 3-stage fp16 GEMM, BM=128 x BN=128, ldmatrix fragment loads.
// 256 threads = 8 warps (4 m x 2 n), warp tile 32x64.
// N-guards allow N not multiple of 128 (576, 192).
// ---------------------------------------------------------------------------
#define HLD 20
#define HA_STAGE (128*HLD)                  // 2560 u32
#define HB_STAGE (128*HLD)                  // 2560 u32
#define HSTAGE_W (HA_STAGE + HB_STAGE)      // 5120 u32
#define GEMM_SMEM_BYTES (3*HSTAGE_W*4)      // 61440 B

template<bool GATHER, bool HOUT>
__global__ __launch_bounds__(256)
void gemm_h_bn(const __half* __restrict__ A, const __half* __restrict__ W,
               const float* __restrict__ bn_g, const float* __restrict__ bn_b,
               const float* __restrict__ bn_m, const float* __restrict__ bn_v,
               void* __restrict__ Cv, int N)
{
    extern __shared__ uint32_t gsm[];

    const int tid  = threadIdx.x;
    const int bm   = blockIdx.y * 128;
    const int bn   = blockIdx.x * 128;
    const int warp = tid >> 5;
    const int lane = tid & 31;
    const int wm   = (warp >> 1) * 32;
    const int wn   = (warp & 1) * 64;
    const int g8   = lane >> 2;
    const int tg   = lane & 3;

    // cp.async mapping: 128 rows x 4 16B-chunks for A and for B -> 2+2 per thread
    const int lrow = tid >> 2;        // 0..63
    const int seg  = tid & 3;

    int asrc[2];
#pragma unroll
    for (int j = 0; j < 2; j++) {
        int m = bm + lrow + 64 * j;
        if (GATHER) {
            int b  = m / NQTOK;
            int qq = m - b * NQTOK;
            int qi = qq / 7;
            int qj = qq - qi * 7;
            asrc[j] = b * NTOK + qi * 2 * RESOL + qj * 2;
        } else {
            asrc[j] = m;
        }
    }

    const uint32_t sbase = (uint32_t)__cvta_generic_to_shared(gsm);

    auto issue = [&](int it, int s) {
        const int k0 = it * 32;
        uint32_t abase = sbase + (uint32_t)(s * HSTAGE_W) * 4u;
#pragma unroll
        for (int j = 0; j < 2; j++) {
            uint32_t dst = abase + (uint32_t)((lrow + 64 * j) * HLD + seg * 4) * 4u;
            cp_async16(dst, A + (size_t)asrc[j] * INDIM + k0 + seg * 8);
        }
        uint32_t bbase = abase + (uint32_t)HA_STAGE * 4u;
#pragma unroll
        for (int j = 0; j < 2; j++) {
            int row = lrow + 64 * j;
            if (bn + row < N) {
                uint32_t dst = bbase + (uint32_t)(row * HLD + seg * 4) * 4u;
                cp_async16(dst, W + (size_t)(bn + row) * INDIM + k0 + seg * 8);
            }
        }
        cp_commit();
    };

    float acc[2][8][4] = {};

    issue(0, 0);
    issue(1, 1);

    // ldmatrix per-lane address components (byte offsets within a stage)
    const int a_lrow0 = wm + (lane & 15);            // + mi*16
    const int a_c16   = lane >> 4;                    // 0/1 (16B col)
    const int b_g     = lane >> 3;                    // 0..3
    const int b_lrow0 = wn + ((b_g >> 1) << 3) + (lane & 7);   // + nj*16
    const int b_c16   = b_g & 1;

    const int NIT = INDIM / 32;
    for (int it = 0; it < NIT; it++) {
        if (it < NIT - 1) asm volatile("cp.async.wait_group 1;\n" ::: "memory");
        else              asm volatile("cp.async.wait_group 0;\n" ::: "memory");
        __syncthreads();
        if (it + 2 < NIT) issue(it + 2, (it + 2) % 3);

        const uint32_t stage_a = sbase + (uint32_t)((it % 3) * HSTAGE_W) * 4u;
        const uint32_t stage_b = stage_a + (uint32_t)HA_STAGE * 4u;

#pragma unroll
        for (int kc = 0; kc < 2; kc++) {
            const int kbB = kc * 32;                  // byte offset of k-slice
            uint32_t af[2][4];
#pragma unroll
            for (int mi = 0; mi < 2; mi++) {
                uint32_t addr = stage_a +
                    (uint32_t)((a_lrow0 + mi * 16) * HLD) * 4u + kbB + a_c16 * 16;
                ldmatrix_x4(af[mi], addr);
            }
            uint32_t bf[8][2];
#pragma unroll
            for (int nj = 0; nj < 4; nj++) {
                uint32_t r[4];
                uint32_t addr = stage_b +
                    (uint32_t)((b_lrow0 + nj * 16) * HLD) * 4u + kbB + b_c16 * 16;
                ldmatrix_x4(r, addr);
                bf[2*nj][0] = r[0]; bf[2*nj][1] = r[1];
                bf[2*nj+1][0] = r[2]; bf[2*nj+1][1] = r[3];
            }
#pragma unroll
            for (int mi = 0; mi < 2; mi++)
#pragma unroll
                for (int ni = 0; ni < 8; ni++)
                    mma_f16(acc[mi][ni], af[mi], bf[ni]);
        }
    }

    // BN epilogue (guarded for partial n-tiles)
#pragma unroll
    for (int ni = 0; ni < 8; ni++) {
        int n0 = bn + wn + ni * 8 + 2 * tg;
        if (n0 >= N) continue;
        float sc0 = bn_g[n0] * rsqrtf(bn_v[n0] + BN_EPS);
        float bi0 = bn_b[n0] - bn_m[n0] * sc0;
        float sc1 = bn_g[n0 + 1] * rsqrtf(bn_v[n0 + 1] + BN_EPS);
        float bi1 = bn_b[n0 + 1] - bn_m[n0 + 1] * sc1;
#pragma unroll
        for (int mi = 0; mi < 2; mi++) {
#pragma unroll
            for (int rr = 0; rr < 2; rr++) {
                int mrow = bm + wm + mi * 16 + g8 + rr * 8;
                float vx = fmaf(acc[mi][ni][rr * 2 + 0], sc0, bi0);
                float vy = fmaf(acc[mi][ni][rr * 2 + 1], sc1, bi1);
                if (HOUT) {
                    __half2 hv = __floats2half2_rn(vx, vy);
                    *(uint32_t*)((__half*)Cv + (size_t)mrow * N + n0) = *(uint32_t*)&hv;
                } else {
                    *(float2*)((float*)Cv + (size_t)mrow * N + n0) = make_float2(vx, vy);
                }
            }
        }
    }
}

// ---------------------------------------------------------------------------
// Precompute bias table
// ---------------------------------------------------------------------------
__global__ __launch_bounds__(256)
void bias_pre_kernel(const float* __restrict__ biases, const int* __restrict__ idxs,
                     float* __restrict__ tab)
{
    int i = blockIdx.x * 256 + threadIdx.x;
    if (i < NQTOK * NTOK) {
        int id = idxs[i];
#pragma unroll
        for (int h = 0; h < HEADS; h++)
            tab[(size_t)h * (NQTOK * NTOK) + i] = biases[h * NTOK + id];
    }
}

// ---------------------------------------------------------------------------
// fp16 tensor-core attention (unchanged from R13 passing version).
// ---------------------------------------------------------------------------
#define QROWS 32
#define LDK 12
#define LDVT 108
#define LDP 108
#define LDS_ 201
#define LDVN 17
#define QS_OFF 0
#define KS_OFF (QS_OFF + QROWS*LDK)
#define VT_OFF (KS_OFF + 200*LDK)
#define SB_OFF (VT_OFF + 32*LDVT)
#define PB_OFF (SB_OFF + QROWS*LDS_)
#define ATTN_SMEM_U32 (PB_OFF + QROWS*LDP)
#define ATTN_SMEM_BYTES (ATTN_SMEM_U32 * 4)

__global__ __launch_bounds__(256)
void attn_h_kernel(const __half* __restrict__ kv, const __half* __restrict__ qg,
                   const float* __restrict__ btab, __half* __restrict__ ao)
{
    extern __shared__ uint32_t sm[];
    uint32_t* Qs = sm + QS_OFF;
    uint32_t* Ks = sm + KS_OFF;
    uint32_t* Vt = sm + VT_OFF;
    uint32_t* Sb = sm + SB_OFF;
    uint32_t* Pb = sm + PB_OFF;
    uint32_t* Vn = Sb;

    const int tid   = threadIdx.x;
    const int half_ = blockIdx.x & 1;
    const int bh    = blockIdx.x >> 1;
    const int b     = bh / HEADS;
    const int h     = bh - b * HEADS;
    const int qbase = half_ * QROWS;
    const int w     = tid >> 5;
    const int lane  = tid & 31;
    const int g8    = lane >> 2;
    const int tg    = lane & 3;
    const float* bt = btab + (size_t)h * (NQTOK * NTOK);

    for (int i = tid; i < QROWS * LDK; i += 256) Qs[i] = 0;
    for (int i = tid; i < 4 * LDK; i += 256) Ks[196 * LDK + i] = 0;
    __syncthreads();

    for (int i = tid; i < QROWS * 8; i += 256) {
        int qi = i >> 3, d2 = i & 7;
        if (qbase + qi < NQTOK)
            Qs[qi * LDK + d2] =
                ((const uint32_t*)(qg + (size_t)(b * NQTOK + qbase + qi) * KEYATTN + h * KD))[d2];
    }
    for (int i = tid; i < NTOK * 8; i += 256) {
        int n = i >> 3, d2 = i & 7;
        Ks[n * LDK + d2] =
            ((const uint32_t*)(kv + (size_t)(b * NTOK + n) * KVD + h * (KD + VD)))[d2];
    }
    for (int i = tid; i < NTOK * 16; i += 256) {
        int n = i >> 4, d2 = i & 15;
        Vn[n * LDVN + d2] =
            ((const uint32_t*)(kv + (size_t)(b * NTOK + n) * KVD + h * (KD + VD) + KD))[d2];
    }
    __syncthreads();

    {
        const __half* Vnh = (const __half*)Vn;
        for (int i = tid; i < 32 * 104; i += 256) {
            int d = i / 104, p = i - (i / 104) * 104;
            uint32_t v = 0;
            if (2 * p + 1 < NTOK) {
                __half2 hv = __halves2half2(Vnh[(2 * p) * (2 * LDVN) + d],
                                            Vnh[(2 * p + 1) * (2 * LDVN) + d]);
                v = *(uint32_t*)&hv;
            }
            Vt[d * LDVT + p] = v;
        }
    }
    __syncthreads();

    {
        const int mt = w >> 2;
        const int nq = w & 3;
        const int nt0 = (nq == 0) ? 0 : (nq == 1) ? 6 : (nq == 2) ? 12 : 18;
        const int nt1 = (nq == 0) ? 6 : (nq == 1) ? 12 : (nq == 2) ? 18 : 25;

        const int r = mt * 16 + g8;
        uint32_t a[4];
        a[0] = Qs[r * LDK + tg];
        a[1] = Qs[(r + 8) * LDK + tg];
        a[2] = Qs[r * LDK + tg + 4];
        a[3] = Qs[(r + 8) * LDK + tg + 4];

        for (int nt = nt0; nt < nt1; nt++) {
            float c[4] = {0.f, 0.f, 0.f, 0.f};
            uint32_t bfr[2];
            bfr[0] = Ks[(nt * 8 + g8) * LDK + tg];
            bfr[1] = Ks[(nt * 8 + g8) * LDK + tg + 4];
            mma_f16(c, a, bfr);

            int r0 = mt * 16 + g8;
            int r1 = r0 + 8;
            int gq0 = qbase + r0;
            int gq1 = qbase + r1;
            int col = nt * 8 + 2 * tg;
            float2 bv0 = make_float2(0.f, 0.f), bv1 = make_float2(0.f, 0.f);
            if (col < NTOK) {
                if (gq0 < NQTOK) bv0 = *(const float2*)(bt + gq0 * NTOK + col);
                if (gq1 < NQTOK) bv1 = *(const float2*)(bt + gq1 * NTOK + col);
            }
            Sb[r0 * LDS_ + col]     = __float_as_uint(fmaf(c[0], ATTNSCALE, bv0.x));
            Sb[r0 * LDS_ + col + 1] = __float_as_uint(fmaf(c[1], ATTNSCALE, bv0.y));
            Sb[r1 * LDS_ + col]     = __float_as_uint(fmaf(c[2], ATTNSCALE, bv1.x));
            Sb[r1 * LDS_ + col + 1] = __float_as_uint(fmaf(c[3], ATTNSCALE, bv1.y));
        }
    }
    __syncthreads();

    for (int r = w; r < QROWS; r += 8) {
        float s0[4], s1[4];
        float mx = -1e30f;
#pragma unroll
        for (int it = 0; it < 4; it++) {
            int p = lane + it * 32;
            if (p < 98) {
                s0[it] = __uint_as_float(Sb[r * LDS_ + 2 * p]);
                s1[it] = __uint_as_float(Sb[r * LDS_ + 2 * p + 1]);
                mx = fmaxf(mx, fmaxf(s0[it], s1[it]));
            } else {
                s0[it] = -1e30f; s1[it] = -1e30f;
            }
        }
#pragma unroll
        for (int o = 16; o > 0; o >>= 1)
            mx = fmaxf(mx, __shfl_xor_sync(0xffffffffu, mx, o));
        float sum = 0.f;
        float e0[4], e1[4];
#pragma unroll
        for (int it = 0; it < 4; it++) {
            int p = lane + it * 32;
            if (p < 98) {
                e0[it] = __expf(s0[it] - mx);
                e1[it] = __expf(s1[it] - mx);
                sum += e0[it] + e1[it];
            } else { e0[it] = 0.f; e1[it] = 0.f; }
        }
#pragma unroll
        for (int o = 16; o > 0; o >>= 1)
            sum += __shfl_xor_sync(0xffffffffu, sum, o);
        float inv = 1.f / sum;
#pragma unroll
        for (int it = 0; it < 4; it++) {
            int p = lane + it * 32;
            if (p < 104) {
                __half2 hv = __floats2half2_rn(e0[it] * inv, e1[it] * inv);
                Pb[r * LDP + p] = *(uint32_t*)&hv;
            }
        }
    }
    __syncthreads();

    {
        const int mt = w >> 2;
        const int dh = w & 3;
        const int r = mt * 16 + g8;
        float acc[4] = {0.f, 0.f, 0.f, 0.f};
#pragma unroll
        for (int ks = 0; ks < 13; ks++) {
            int ku = ks * 8;
            uint32_t a[4];
            a[0] = Pb[r * LDP + ku + tg];
            a[1] = Pb[(r + 8) * LDP + ku + tg];
            a[2] = Pb[r * LDP + ku + tg + 4];
            a[3] = Pb[(r + 8) * LDP + ku + tg + 4];
            uint32_t bfr[2];
            bfr[0] = Vt[(dh * 8 + g8) * LDVT + ku + tg];
            bfr[1] = Vt[(dh * 8 + g8) * LDVT + ku + tg + 4];
            mma_f16(acc, a, bfr);
        }
        int d0  = dh * 8 + 2 * tg;
        int gq0 = qbase + mt * 16 + g8;
        int gq1 = gq0 + 8;
        if (gq0 < NQTOK) {
            float o0 = acc[0], o1 = acc[1];
            __half2 v = __floats2half2_rn(o0 / (1.f + __expf(-o0)),
                                          o1 / (1.f + __expf(-o1)));
            *(uint32_t*)(ao + (size_t)(b * NQTOK + gq0) * VALATTN + h * VD + d0) =
                *(uint32_t*)&v;
        }
        if (gq1 < NQTOK) {
            float o0 = acc[2], o1 = acc[3];
            __half2 v = __floats2half2_rn(o0 / (1.f + __expf(-o0)),
                                          o1 / (1.f + __expf(-o1)));
            *(uint32_t*)(ao + (size_t)(b * NQTOK + gq1) * VALATTN + h * VD + d0) =
                *(uint32_t*)&v;
        }
    }
}

// ---------------------------------------------------------------------------
// Launch
// ---------------------------------------------------------------------------
extern "C" void kernel_launch(void* const* d_in, const int* in_sizes, int n_in,
                              void* d_out, int out_size)
{
    const float* x     = (const float*)d_in[0];
    const float* kv_w  = (const float*)d_in[1];
    const float* kv_g  = (const float*)d_in[2];
    const float* kv_b  = (const float*)d_in[3];
    const float* kv_m  = (const float*)d_in[4];
    const float* kv_v  = (const float*)d_in[5];
    const float* q_w   = (const float*)d_in[6];
    const float* q_g   = (const float*)d_in[7];
    const float* q_b   = (const float*)d_in[8];
    const float* q_m   = (const float*)d_in[9];
    const float* q_v   = (const float*)d_in[10];
    const float* pj_w  = (const float*)d_in[11];
    const float* pj_g  = (const float*)d_in[12];
    const float* pj_b  = (const float*)d_in[13];
    const float* pj_m  = (const float*)d_in[14];
    const float* pj_v  = (const float*)d_in[15];
    const float* biases    = (const float*)d_in[16];
    const int*   bias_idxs = (const int*)d_in[17];
    float* out = (float*)d_out;

    float  *btab;
    __half *kvh, *qh, *aoh, *xh, *wh;
    cudaGetSymbolAddress((void**)&kvh,  g_kvh);
    cudaGetSymbolAddress((void**)&qh,   g_qh);
    cudaGetSymbolAddress((void**)&aoh,  g_aoh);
    cudaGetSymbolAddress((void**)&btab, g_btab);
    cudaGetSymbolAddress((void**)&xh,   g_xh);
    cudaGetSymbolAddress((void**)&wh,   g_wh);

    cudaFuncSetAttribute(attn_h_kernel,
                         cudaFuncAttributeMaxDynamicSharedMemorySize, ATTN_SMEM_BYTES);
    cudaFuncSetAttribute(gemm_h_bn<false, true>,
                         cudaFuncAttributeMaxDynamicSharedMemorySize, GEMM_SMEM_BYTES);
    cudaFuncSetAttribute(gemm_h_bn<true, true>,
                         cudaFuncAttributeMaxDynamicSharedMemorySize, GEMM_SMEM_BYTES);
    cudaFuncSetAttribute(gemm_h_bn<false, false>,
                         cudaFuncAttributeMaxDynamicSharedMemorySize, GEMM_SMEM_BYTES);

    conv_all_kernel<<<(N4_ALL + 255) / 256, 256>>>(
        (const float4*)x, (const float4*)kv_w, (const float4*)q_w, (const float4*)pj_w,
        (uint2*)xh, (uint2*)wh);

    bias_pre_kernel<<<(NQTOK * NTOK + 255) / 256, 256>>>(biases, bias_idxs, btab);

    // GEMM1: kv = BN(x @ kv_w^T)   [50176 x 576] -> fp16, 5 n-tiles of 128
    gemm_h_bn<false, true><<<dim3((KVD + 127) / 128, M1 / 128), 256, GEMM_SMEM_BYTES>>>(
        xh, wh + WR_KV, kv_g, kv_b, kv_m, kv_v, kvh, KVD);

    // GEMM2: q = BN(xq @ q_w^T)    [12544 x 192] -> fp16, gathered rows
    gemm_h_bn<true, true><<<dim3((KEYATTN + 127) / 128, M2 / 128), 256, GEMM_SMEM_BYTES>>>(
        xh, wh + WR_Q, q_g, q_b, q_m, q_v, qh, KEYATTN);

    // Attention (fp16 mma), writes fp16
    attn_h_kernel<<<BATCH * HEADS * 2, 256, ATTN_SMEM_BYTES>>>(
        kvh, qh, btab, aoh);

    // GEMM3: out = BN(silu_attn @ pj_w^T)  [12544 x 512] -> f32
    gemm_h_bn<false, false><<<dim3(OUTDIM / 128, M2 / 128), 256, GEMM_SMEM_BYTES>>>(
        aoh, wh + WR_PJ, pj_g, pj_b, pj_m, pj_v, out, OUTDIM);
}

// round 15
// speedup vs baseline: 1.3665x; 1.0579x over previous
#include <cuda_runtime.h>
#include <cuda_fp16.h>
#include <math.h>
#include <stdint.h>

// ---------------------------------------------------------------------------
// Problem constants
// ---------------------------------------------------------------------------
#define BATCH    256
#define RESOL    14
#define NTOK     196
#define NQTOK    49
#define INDIM    384
#define HEADS    12
#define KD       16
#define VD       32
#define KVD      576
#define KEYATTN  192
#define VALATTN  384
#define OUTDIM   512
#define ATTNSCALE 0.25f
#define BN_EPS   1e-5f

#define M1 (BATCH*NTOK)   // 50176
#define M2 (BATCH*NQTOK)  // 12544

#define WR_KV 0
#define WR_Q  (576*INDIM)
#define WR_PJ (768*INDIM)

// Scratch (device globals)
__device__ __half g_kvh[(size_t)M1 * KVD];
__device__ __half g_qh [(size_t)M2 * KEYATTN];
__device__ __half g_aoh[(size_t)M2 * VALATTN];
__device__ float  g_btab[(size_t)HEADS * NQTOK * NTOK];
__device__ __half g_xh [(size_t)M1 * INDIM];
__device__ __half g_wh [(size_t)1280 * INDIM];

// ---------------------------------------------------------------------------
// helpers
// ---------------------------------------------------------------------------
__device__ __forceinline__ void mma_f16(float* c, const uint32_t* a, const uint32_t* b) {
    asm volatile(
        "mma.sync.aligned.m16n8k16.row.col.f32.f16.f16.f32 "
        "{%0,%1,%2,%3}, {%4,%5,%6,%7}, {%8,%9}, {%0,%1,%2,%3};\n"
        : "+f"(c[0]), "+f"(c[1]), "+f"(c[2]), "+f"(c[3])
        : "r"(a[0]), "r"(a[1]), "r"(a[2]), "r"(a[3]), "r"(b[0]), "r"(b[1]));
}

__device__ __forceinline__ void ldmatrix_x4(uint32_t* r, uint32_t addr) {
    asm volatile("ldmatrix.sync.aligned.m8n8.x4.shared.b16 {%0,%1,%2,%3}, [%4];"
                 : "=r"(r[0]), "=r"(r[1]), "=r"(r[2]), "=r"(r[3]) : "r"(addr));
}

__device__ __forceinline__ void cp_async16(uint32_t dst, const void* src) {
    asm volatile("cp.async.cg.shared.global [%0], [%1], 16;\n" :: "r"(dst), "l"(src));
}
__device__ __forceinline__ void cp_commit() {
    asm volatile("cp.async.commit_group;\n" ::: "memory");
}

// ---------------------------------------------------------------------------
// Merged f32 -> f16 conversion (x + 3 weights), one launch
// ---------------------------------------------------------------------------
#define N4_X   ((M1*INDIM)/4)
#define N4_KV  ((KVD*INDIM)/4)
#define N4_Q   ((KEYATTN*INDIM)/4)
#define N4_PJ  ((OUTDIM*INDIM)/4)
#define N4_ALL (N4_X + N4_KV + N4_Q + N4_PJ)

__global__ __launch_bounds__(256)
void conv_all_kernel(const float4* __restrict__ x,  const float4* __restrict__ kvw,
                     const float4* __restrict__ qw, const float4* __restrict__ pjw,
                     uint2* __restrict__ xh, uint2* __restrict__ wh)
{
    int i = blockIdx.x * 256 + threadIdx.x;
    if (i >= N4_ALL) return;
    const float4* src;
    uint2* dst;
    int j = i;
    if (j < N4_X)                    { src = x;   dst = xh;                 }
    else if ((j -= N4_X) < N4_KV)    { src = kvw; dst = wh + WR_KV/4;       }
    else if ((j -= N4_KV) < N4_Q)    { src = qw;  dst = wh + WR_Q/4;        }
    else { j -= N4_Q;                  src = pjw; dst = wh + WR_PJ/4;       }
    float4 v = src[j];
    __half2 h0 = __floats2half2_rn(v.x, v.y);
    __half2 h1 = __floats2half2_rn(v.z, v.w);
    uint2 o;
    o.x = *(uint32_t*)&h0;
    o.y = *(uint32_t*)&h1;
    dst[j] = o;
}

// ---------------------------------------------------------------------------
// cp.async 3-stage fp16 GEMM, BM=128 x BN=64, BK=64, ldmatrix fragment loads.
// 256 threads = 8 warps (4 m x 2 n), warp tile 32x32. 6 K-iterations.
// All N are multiples of 64 -> no guards.
// Smem row = 64 halfs = 32 u32 data + 4 pad (HLD2=36).
// ---------------------------------------------------------------------------
#define HLD2 36
#define GA_STAGE (128*HLD2)                 // 4608 u32
#define GB_STAGE (64*HLD2)                  // 2304 u32
#define GSTAGE_W (GA_STAGE + GB_STAGE)      // 6912 u32
#define GEMM_SMEM_BYTES (3*GSTAGE_W*4)      // 82944 B

template<bool GATHER, bool HOUT>
__global__ __launch_bounds__(256)
void gemm_h_bn(const __half* __restrict__ A, const __half* __restrict__ W,
               const float* __restrict__ bn_g, const float* __restrict__ bn_b,
               const float* __restrict__ bn_m, const float* __restrict__ bn_v,
               void* __restrict__ Cv, int N)
{
    extern __shared__ uint32_t gsm[];

    const int tid  = threadIdx.x;
    const int bm   = blockIdx.y * 128;
    const int bn   = blockIdx.x * 64;
    const int warp = tid >> 5;
    const int lane = tid & 31;
    const int wm   = (warp >> 1) * 32;
    const int wn   = (warp & 1) * 32;
    const int g8   = lane >> 2;
    const int tg   = lane & 3;

    // cp.async mapping: rows of 8 x 16B chunks. A: 128 rows -> 4 chunks/thread;
    // B: 64 rows -> 2 chunks/thread. row = tid>>3 (+32j), seg = tid&7.
    const int lrow = tid >> 3;        // 0..31
    const int seg  = tid & 7;

    int asrc[4];
#pragma unroll
    for (int j = 0; j < 4; j++) {
        int m = bm + lrow + 32 * j;
        if (GATHER) {
            int b  = m / NQTOK;
            int qq = m - b * NQTOK;
            int qi = qq / 7;
            int qj = qq - qi * 7;
            asrc[j] = b * NTOK + qi * 2 * RESOL + qj * 2;
        } else {
            asrc[j] = m;
        }
    }

    const uint32_t sbase = (uint32_t)__cvta_generic_to_shared(gsm);

    auto issue = [&](int it, int s) {
        const int k0 = it * 64;
        uint32_t abase = sbase + (uint32_t)(s * GSTAGE_W) * 4u;
#pragma unroll
        for (int j = 0; j < 4; j++) {
            uint32_t dst = abase + (uint32_t)((lrow + 32 * j) * HLD2 + seg * 4) * 4u;
            cp_async16(dst, A + (size_t)asrc[j] * INDIM + k0 + seg * 8);
        }
        uint32_t bbase = abase + (uint32_t)GA_STAGE * 4u;
#pragma unroll
        for (int j = 0; j < 2; j++) {
            int row = lrow + 32 * j;
            uint32_t dst = bbase + (uint32_t)(row * HLD2 + seg * 4) * 4u;
            cp_async16(dst, W + (size_t)(bn + row) * INDIM + k0 + seg * 8);
        }
        cp_commit();
    };

    float acc[2][4][4] = {};

    issue(0, 0);
    issue(1, 1);

    // ldmatrix per-lane address components
    const int a_lrow0 = wm + (lane & 15);
    const int a_c16   = lane >> 4;
    const int b_g     = lane >> 3;
    const int b_lrow0 = wn + ((b_g >> 1) << 3) + (lane & 7);
    const int b_c16   = b_g & 1;

    const int NIT = INDIM / 64;   // 6
    for (int it = 0; it < NIT; it++) {
        if (it < NIT - 1) asm volatile("cp.async.wait_group 1;\n" ::: "memory");
        else              asm volatile("cp.async.wait_group 0;\n" ::: "memory");
        __syncthreads();
        if (it + 2 < NIT) issue(it + 2, (it + 2) % 3);

        const uint32_t stage_a = sbase + (uint32_t)((it % 3) * GSTAGE_W) * 4u;
        const uint32_t stage_b = stage_a + (uint32_t)GA_STAGE * 4u;

#pragma unroll
        for (int kc = 0; kc < 4; kc++) {
            const int kbB = kc * 32;   // byte offset of k=16 slice within row
            uint32_t af[2][4];
#pragma unroll
            for (int mi = 0; mi < 2; mi++) {
                uint32_t addr = stage_a +
                    (uint32_t)((a_lrow0 + mi * 16) * HLD2) * 4u + kbB + a_c16 * 16;
                ldmatrix_x4(af[mi], addr);
            }
            uint32_t bf[4][2];
#pragma unroll
            for (int nj = 0; nj < 2; nj++) {
                uint32_t r[4];
                uint32_t addr = stage_b +
                    (uint32_t)((b_lrow0 + nj * 16) * HLD2) * 4u + kbB + b_c16 * 16;
                ldmatrix_x4(r, addr);
                bf[2*nj][0] = r[0]; bf[2*nj][1] = r[1];
                bf[2*nj+1][0] = r[2]; bf[2*nj+1][1] = r[3];
            }
#pragma unroll
            for (int mi = 0; mi < 2; mi++)
#pragma unroll
                for (int ni = 0; ni < 4; ni++)
                    mma_f16(acc[mi][ni], af[mi], bf[ni]);
        }
    }

    // BN epilogue
#pragma unroll
    for (int ni = 0; ni < 4; ni++) {
        int n0 = bn + wn + ni * 8 + 2 * tg;
        float sc0 = bn_g[n0] * rsqrtf(bn_v[n0] + BN_EPS);
        float bi0 = bn_b[n0] - bn_m[n0] * sc0;
        float sc1 = bn_g[n0 + 1] * rsqrtf(bn_v[n0 + 1] + BN_EPS);
        float bi1 = bn_b[n0 + 1] - bn_m[n0 + 1] * sc1;
#pragma unroll
        for (int mi = 0; mi < 2; mi++) {
#pragma unroll
            for (int rr = 0; rr < 2; rr++) {
                int mrow = bm + wm + mi * 16 + g8 + rr * 8;
                float vx = fmaf(acc[mi][ni][rr * 2 + 0], sc0, bi0);
                float vy = fmaf(acc[mi][ni][rr * 2 + 1], sc1, bi1);
                if (HOUT) {
                    __half2 hv = __floats2half2_rn(vx, vy);
                    *(uint32_t*)((__half*)Cv + (size_t)mrow * N + n0) = *(uint32_t*)&hv;
                } else {
                    *(float2*)((float*)Cv + (size_t)mrow * N + n0) = make_float2(vx, vy);
                }
            }
        }
    }
}

// ---------------------------------------------------------------------------
// Precompute bias table
// ---------------------------------------------------------------------------
__global__ __launch_bounds__(256)
void bias_pre_kernel(const float* __restrict__ biases, const int* __restrict__ idxs,
                     float* __restrict__ tab)
{
    int i = blockIdx.x * 256 + threadIdx.x;
    if (i < NQTOK * NTOK) {
        int id = idxs[i];
#pragma unroll
        for (int h = 0; h < HEADS; h++)
            tab[(size_t)h * (NQTOK * NTOK) + i] = biases[h * NTOK + id];
    }
}

// ---------------------------------------------------------------------------
// fp16 tensor-core attention (unchanged from R13/R14 passing version).
// ---------------------------------------------------------------------------
#define QROWS 32
#define LDK 12
#define LDVT 108
#define LDP 108
#define LDS_ 201
#define LDVN 17
#define QS_OFF 0
#define KS_OFF (QS_OFF + QROWS*LDK)
#define VT_OFF (KS_OFF + 200*LDK)
#define SB_OFF (VT_OFF + 32*LDVT)
#define PB_OFF (SB_OFF + QROWS*LDS_)
#define ATTN_SMEM_U32 (PB_OFF + QROWS*LDP)
#define ATTN_SMEM_BYTES (ATTN_SMEM_U32 * 4)

__global__ __launch_bounds__(256)
void attn_h_kernel(const __half* __restrict__ kv, const __half* __restrict__ qg,
                   const float* __restrict__ btab, __half* __restrict__ ao)
{
    extern __shared__ uint32_t sm[];
    uint32_t* Qs = sm + QS_OFF;
    uint32_t* Ks = sm + KS_OFF;
    uint32_t* Vt = sm + VT_OFF;
    uint32_t* Sb = sm + SB_OFF;
    uint32_t* Pb = sm + PB_OFF;
    uint32_t* Vn = Sb;

    const int tid   = threadIdx.x;
    const int half_ = blockIdx.x & 1;
    const int bh    = blockIdx.x >> 1;
    const int b     = bh / HEADS;
    const int h     = bh - b * HEADS;
    const int qbase = half_ * QROWS;
    const int w     = tid >> 5;
    const int lane  = tid & 31;
    const int g8    = lane >> 2;
    const int tg    = lane & 3;
    const float* bt = btab + (size_t)h * (NQTOK * NTOK);

    for (int i = tid; i < QROWS * LDK; i += 256) Qs[i] = 0;
    for (int i = tid; i < 4 * LDK; i += 256) Ks[196 * LDK + i] = 0;
    __syncthreads();

    for (int i = tid; i < QROWS * 8; i += 256) {
        int qi = i >> 3, d2 = i & 7;
        if (qbase + qi < NQTOK)
            Qs[qi * LDK + d2] =
                ((const uint32_t*)(qg + (size_t)(b * NQTOK + qbase + qi) * KEYATTN + h * KD))[d2];
    }
    for (int i = tid; i < NTOK * 8; i += 256) {
        int n = i >> 3, d2 = i & 7;
        Ks[n * LDK + d2] =
            ((const uint32_t*)(kv + (size_t)(b * NTOK + n) * KVD + h * (KD + VD)))[d2];
    }
    for (int i = tid; i < NTOK * 16; i += 256) {
        int n = i >> 4, d2 = i & 15;
        Vn[n * LDVN + d2] =
            ((const uint32_t*)(kv + (size_t)(b * NTOK + n) * KVD + h * (KD + VD) + KD))[d2];
    }
    __syncthreads();

    {
        const __half* Vnh = (const __half*)Vn;
        for (int i = tid; i < 32 * 104; i += 256) {
            int d = i / 104, p = i - (i / 104) * 104;
            uint32_t v = 0;
            if (2 * p + 1 < NTOK) {
                __half2 hv = __halves2half2(Vnh[(2 * p) * (2 * LDVN) + d],
                                            Vnh[(2 * p + 1) * (2 * LDVN) + d]);
                v = *(uint32_t*)&hv;
            }
            Vt[d * LDVT + p] = v;
        }
    }
    __syncthreads();

    {
        const int mt = w >> 2;
        const int nq = w & 3;
        const int nt0 = (nq == 0) ? 0 : (nq == 1) ? 6 : (nq == 2) ? 12 : 18;
        const int nt1 = (nq == 0) ? 6 : (nq == 1) ? 12 : (nq == 2) ? 18 : 25;

        const int r = mt * 16 + g8;
        uint32_t a[4];
        a[0] = Qs[r * LDK + tg];
        a[1] = Qs[(r + 8) * LDK + tg];
        a[2] = Qs[r * LDK + tg + 4];
        a[3] = Qs[(r + 8) * LDK + tg + 4];

        for (int nt = nt0; nt < nt1; nt++) {
            float c[4] = {0.f, 0.f, 0.f, 0.f};
            uint32_t bfr[2];
            bfr[0] = Ks[(nt * 8 + g8) * LDK + tg];
            bfr[1] = Ks[(nt * 8 + g8) * LDK + tg + 4];
            mma_f16(c, a, bfr);

            int r0 = mt * 16 + g8;
            int r1 = r0 + 8;
            int gq0 = qbase + r0;
            int gq1 = qbase + r1;
            int col = nt * 8 + 2 * tg;
            float2 bv0 = make_float2(0.f, 0.f), bv1 = make_float2(0.f, 0.f);
            if (col < NTOK) {
                if (gq0 < NQTOK) bv0 = *(const float2*)(bt + gq0 * NTOK + col);
                if (gq1 < NQTOK) bv1 = *(const float2*)(bt + gq1 * NTOK + col);
            }
            Sb[r0 * LDS_ + col]     = __float_as_uint(fmaf(c[0], ATTNSCALE, bv0.x));
            Sb[r0 * LDS_ + col + 1] = __float_as_uint(fmaf(c[1], ATTNSCALE, bv0.y));
            Sb[r1 * LDS_ + col]     = __float_as_uint(fmaf(c[2], ATTNSCALE, bv1.x));
            Sb[r1 * LDS_ + col + 1] = __float_as_uint(fmaf(c[3], ATTNSCALE, bv1.y));
        }
    }
    __syncthreads();

    for (int r = w; r < QROWS; r += 8) {
        float s0[4], s1[4];
        float mx = -1e30f;
#pragma unroll
        for (int it = 0; it < 4; it++) {
            int p = lane + it * 32;
            if (p < 98) {
                s0[it] = __uint_as_float(Sb[r * LDS_ + 2 * p]);
                s1[it] = __uint_as_float(Sb[r * LDS_ + 2 * p + 1]);
                mx = fmaxf(mx, fmaxf(s0[it], s1[it]));
            } else {
                s0[it] = -1e30f; s1[it] = -1e30f;
            }
        }
#pragma unroll
        for (int o = 16; o > 0; o >>= 1)
            mx = fmaxf(mx, __shfl_xor_sync(0xffffffffu, mx, o));
        float sum = 0.f;
        float e0[4], e1[4];
#pragma unroll
        for (int it = 0; it < 4; it++) {
            int p = lane + it * 32;
            if (p < 98) {
                e0[it] = __expf(s0[it] - mx);
                e1[it] = __expf(s1[it] - mx);
                sum += e0[it] + e1[it];
            } else { e0[it] = 0.f; e1[it] = 0.f; }
        }
#pragma unroll
        for (int o = 16; o > 0; o >>= 1)
            sum += __shfl_xor_sync(0xffffffffu, sum, o);
        float inv = 1.f / sum;
#pragma unroll
        for (int it = 0; it < 4; it++) {
            int p = lane + it * 32;
            if (p < 104) {
                __half2 hv = __floats2half2_rn(e0[it] * inv, e1[it] * inv);
                Pb[r * LDP + p] = *(uint32_t*)&hv;
            }
        }
    }
    __syncthreads();

    {
        const int mt = w >> 2;
        const int dh = w & 3;
        const int r = mt * 16 + g8;
        float acc[4] = {0.f, 0.f, 0.f, 0.f};
#pragma unroll
        for (int ks = 0; ks < 13; ks++) {
            int ku = ks * 8;
            uint32_t a[4];
            a[0] = Pb[r * LDP + ku + tg];
            a[1] = Pb[(r + 8) * LDP + ku + tg];
            a[2] = Pb[r * LDP + ku + tg + 4];
            a[3] = Pb[(r + 8) * LDP + ku + tg + 4];
            uint32_t bfr[2];
            bfr[0] = Vt[(dh * 8 + g8) * LDVT + ku + tg];
            bfr[1] = Vt[(dh * 8 + g8) * LDVT + ku + tg + 4];
            mma_f16(acc, a, bfr);
        }
        int d0  = dh * 8 + 2 * tg;
        int gq0 = qbase + mt * 16 + g8;
        int gq1 = gq0 + 8;
        if (gq0 < NQTOK) {
            float o0 = acc[0], o1 = acc[1];
            __half2 v = __floats2half2_rn(o0 / (1.f + __expf(-o0)),
                                          o1 / (1.f + __expf(-o1)));
            *(uint32_t*)(ao + (size_t)(b * NQTOK + gq0) * VALATTN + h * VD + d0) =
                *(uint32_t*)&v;
        }
        if (gq1 < NQTOK) {
            float o0 = acc[2], o1 = acc[3];
            __half2 v = __floats2half2_rn(o0 / (1.f + __expf(-o0)),
                                          o1 / (1.f + __expf(-o1)));
            *(uint32_t*)(ao + (size_t)(b * NQTOK + gq1) * VALATTN + h * VD + d0) =
                *(uint32_t*)&v;
        }
    }
}

// ---------------------------------------------------------------------------
// Launch
// ---------------------------------------------------------------------------
extern "C" void kernel_launch(void* const* d_in, const int* in_sizes, int n_in,
                              void* d_out, int out_size)
{
    const float* x     = (const float*)d_in[0];
    const float* kv_w  = (const float*)d_in[1];
    const float* kv_g  = (const float*)d_in[2];
    const float* kv_b  = (const float*)d_in[3];
    const float* kv_m  = (const float*)d_in[4];
    const float* kv_v  = (const float*)d_in[5];
    const float* q_w   = (const float*)d_in[6];
    const float* q_g   = (const float*)d_in[7];
    const float* q_b   = (const float*)d_in[8];
    const float* q_m   = (const float*)d_in[9];
    const float* q_v   = (const float*)d_in[10];
    const float* pj_w  = (const float*)d_in[11];
    const float* pj_g  = (const float*)d_in[12];
    const float* pj_b  = (const float*)d_in[13];
    const float* pj_m  = (const float*)d_in[14];
    const float* pj_v  = (const float*)d_in[15];
    const float* biases    = (const float*)d_in[16];
    const int*   bias_idxs = (const int*)d_in[17];
    float* out = (float*)d_out;

    float  *btab;
    __half *kvh, *qh, *aoh, *xh, *wh;
    cudaGetSymbolAddress((void**)&kvh,  g_kvh);
    cudaGetSymbolAddress((void**)&qh,   g_qh);
    cudaGetSymbolAddress((void**)&aoh,  g_aoh);
    cudaGetSymbolAddress((void**)&btab, g_btab);
    cudaGetSymbolAddress((void**)&xh,   g_xh);
    cudaGetSymbolAddress((void**)&wh,   g_wh);

    cudaFuncSetAttribute(attn_h_kernel,
                         cudaFuncAttributeMaxDynamicSharedMemorySize, ATTN_SMEM_BYTES);
    cudaFuncSetAttribute(gemm_h_bn<false, true>,
                         cudaFuncAttributeMaxDynamicSharedMemorySize, GEMM_SMEM_BYTES);
    cudaFuncSetAttribute(gemm_h_bn<true, true>,
                         cudaFuncAttributeMaxDynamicSharedMemorySize, GEMM_SMEM_BYTES);
    cudaFuncSetAttribute(gemm_h_bn<false, false>,
                         cudaFuncAttributeMaxDynamicSharedMemorySize, GEMM_SMEM_BYTES);

    conv_all_kernel<<<(N4_ALL + 255) / 256, 256>>>(
        (const float4*)x, (const float4*)kv_w, (const float4*)q_w, (const float4*)pj_w,
        (uint2*)xh, (uint2*)wh);

    bias_pre_kernel<<<(NQTOK * NTOK + 255) / 256, 256>>>(biases, bias_idxs, btab);

    // GEMM1: kv = BN(x @ kv_w^T)   [50176 x 576] -> fp16, 9 n-tiles of 64
    gemm_h_bn<false, true><<<dim3(KVD / 64, M1 / 128), 256, GEMM_SMEM_BYTES>>>(
        xh, wh + WR_KV, kv_g, kv_b, kv_m, kv_v, kvh, KVD);

    // GEMM2: q = BN(xq @ q_w^T)    [12544 x 192] -> fp16, gathered rows
    gemm_h_bn<true, true><<<dim3(KEYATTN / 64, M2 / 128), 256, GEMM_SMEM_BYTES>>>(
        xh, wh + WR_Q, q_g, q_b, q_m, q_v, qh, KEYATTN);

    // Attention (fp16 mma), writes fp16
    attn_h_kernel<<<BATCH * HEADS * 2, 256, ATTN_SMEM_BYTES>>>(
        kvh, qh, btab, aoh);

    // GEMM3: out = BN(silu_attn @ pj_w^T)  [12544 x 512] -> f32
    gemm_h_bn<false, false><<<dim3(OUTDIM / 64, M2 / 128), 256, GEMM_SMEM_BYTES>>>(
        aoh, wh + WR_PJ, pj_g, pj_b, pj_m, pj_v, out, OUTDIM);
}

// round 16
// speedup vs baseline: 1.4861x; 1.0875x over previous
#include <cuda_runtime.h>
#include <cuda_fp16.h>
#include <math.h>
#include <stdint.h>

// ---------------------------------------------------------------------------
// Problem constants
// ---------------------------------------------------------------------------
#define BATCH    256
#define RESOL    14
#define NTOK     196
#define NQTOK    49
#define INDIM    384
#define HEADS    12
#define KD       16
#define VD       32
#define KVD      576
#define KEYATTN  192
#define VALATTN  384
#define OUTDIM   512
#define ATTNSCALE 0.25f
#define BN_EPS   1e-5f

#define M1 (BATCH*NTOK)   // 50176
#define M2 (BATCH*NQTOK)  // 12544

#define WR_KV 0
#define WR_Q  (576*INDIM)
#define WR_PJ (768*INDIM)

// Scratch (device globals)
__device__ __half g_kvh[(size_t)M1 * KVD];
__device__ __half g_qh [(size_t)M2 * KEYATTN];
__device__ __half g_aoh[(size_t)M2 * VALATTN];
__device__ float  g_btab[(size_t)HEADS * NQTOK * NTOK];
__device__ __half g_xh [(size_t)M1 * INDIM];
__device__ __half g_wh [(size_t)1280 * INDIM];

// ---------------------------------------------------------------------------
// helpers
// ---------------------------------------------------------------------------
__device__ __forceinline__ void mma_f16(float* c, const uint32_t* a, const uint32_t* b) {
    asm volatile(
        "mma.sync.aligned.m16n8k16.row.col.f32.f16.f16.f32 "
        "{%0,%1,%2,%3}, {%4,%5,%6,%7}, {%8,%9}, {%0,%1,%2,%3};\n"
        : "+f"(c[0]), "+f"(c[1]), "+f"(c[2]), "+f"(c[3])
        : "r"(a[0]), "r"(a[1]), "r"(a[2]), "r"(a[3]), "r"(b[0]), "r"(b[1]));
}

__device__ __forceinline__ void ldmatrix_x4(uint32_t* r, uint32_t addr) {
    asm volatile("ldmatrix.sync.aligned.m8n8.x4.shared.b16 {%0,%1,%2,%3}, [%4];"
                 : "=r"(r[0]), "=r"(r[1]), "=r"(r[2]), "=r"(r[3]) : "r"(addr));
}

__device__ __forceinline__ void cp_async16(uint32_t dst, const void* src) {
    asm volatile("cp.async.cg.shared.global [%0], [%1], 16;\n" :: "r"(dst), "l"(src));
}
__device__ __forceinline__ void cp_commit() {
    asm volatile("cp.async.commit_group;\n" ::: "memory");
}

// ---------------------------------------------------------------------------
// Merged f32 -> f16 conversion (x + 3 weights), one launch
// ---------------------------------------------------------------------------
#define N4_X   ((M1*INDIM)/4)
#define N4_KV  ((KVD*INDIM)/4)
#define N4_Q   ((KEYATTN*INDIM)/4)
#define N4_PJ  ((OUTDIM*INDIM)/4)
#define N4_ALL (N4_X + N4_KV + N4_Q + N4_PJ)

__global__ __launch_bounds__(256)
void conv_all_kernel(const float4* __restrict__ x,  const float4* __restrict__ kvw,
                     const float4* __restrict__ qw, const float4* __restrict__ pjw,
                     uint2* __restrict__ xh, uint2* __restrict__ wh)
{
    int i = blockIdx.x * 256 + threadIdx.x;
    if (i >= N4_ALL) return;
    const float4* src;
    uint2* dst;
    int j = i;
    if (j < N4_X)                    { src = x;   dst = xh;                 }
    else if ((j -= N4_X) < N4_KV)    { src = kvw; dst = wh + WR_KV/4;       }
    else if ((j -= N4_KV) < N4_Q)    { src = qw;  dst = wh + WR_Q/4;        }
    else { j -= N4_Q;                  src = pjw; dst = wh + WR_PJ/4;       }
    float4 v = src[j];
    __half2 h0 = __floats2half2_rn(v.x, v.y);
    __half2 h1 = __floats2half2_rn(v.z, v.w);
    uint2 o;
    o.x = *(uint32_t*)&h0;
    o.y = *(uint32_t*)&h1;
    dst[j] = o;
}

// ---------------------------------------------------------------------------
// cp.async 3-stage fp16 GEMM, BM=128 x BN=64, BK=64, ldmatrix + XOR swizzle.
// Rows are 128B (64 halfs); 16B chunk c of row r lives at chunk (c ^ (r&7)).
// No padding -> stage 24.6 KB, 3 stages 73.7 KB -> 3 CTAs/SM.
// 256 threads = 8 warps (4 m x 2 n), warp tile 32x32. 6 K-iterations.
// ---------------------------------------------------------------------------
#define GROW 32                              // u32 per row
#define GA_STAGE (128*GROW)                  // 4096 u32
#define GB_STAGE (64*GROW)                   // 2048 u32
#define GSTAGE_W (GA_STAGE + GB_STAGE)       // 6144 u32
#define GEMM_SMEM_BYTES (3*GSTAGE_W*4)       // 73728 B

template<bool GATHER, bool HOUT>
__global__ __launch_bounds__(256)
void gemm_h_bn(const __half* __restrict__ A, const __half* __restrict__ W,
               const float* __restrict__ bn_g, const float* __restrict__ bn_b,
               const float* __restrict__ bn_m, const float* __restrict__ bn_v,
               void* __restrict__ Cv, int N)
{
    extern __shared__ uint32_t gsm[];

    const int tid  = threadIdx.x;
    const int bm   = blockIdx.y * 128;
    const int bn   = blockIdx.x * 64;
    const int warp = tid >> 5;
    const int lane = tid & 31;
    const int wm   = (warp >> 1) * 32;
    const int wn   = (warp & 1) * 32;
    const int g8   = lane >> 2;
    const int tg   = lane & 3;

    const int lrow = tid >> 3;        // 0..31
    const int seg  = tid & 7;         // 16B chunk 0..7

    int asrc[4];
#pragma unroll
    for (int j = 0; j < 4; j++) {
        int m = bm + lrow + 32 * j;
        if (GATHER) {
            int b  = m / NQTOK;
            int qq = m - b * NQTOK;
            int qi = qq / 7;
            int qj = qq - qi * 7;
            asrc[j] = b * NTOK + qi * 2 * RESOL + qj * 2;
        } else {
            asrc[j] = m;
        }
    }

    const uint32_t sbase = (uint32_t)__cvta_generic_to_shared(gsm);

    auto issue = [&](int it, int s) {
        const int k0 = it * 64;
        uint32_t abase = sbase + (uint32_t)(s * GSTAGE_W) * 4u;
#pragma unroll
        for (int j = 0; j < 4; j++) {
            int row = lrow + 32 * j;
            int sw  = seg ^ (row & 7);
            uint32_t dst = abase + (uint32_t)(row * 128 + sw * 16);
            cp_async16(dst, A + (size_t)asrc[j] * INDIM + k0 + seg * 8);
        }
        uint32_t bbase = abase + (uint32_t)GA_STAGE * 4u;
#pragma unroll
        for (int j = 0; j < 2; j++) {
            int row = lrow + 32 * j;
            int sw  = seg ^ (row & 7);
            uint32_t dst = bbase + (uint32_t)(row * 128 + sw * 16);
            cp_async16(dst, W + (size_t)(bn + row) * INDIM + k0 + seg * 8);
        }
        cp_commit();
    };

    float acc[2][4][4] = {};

    issue(0, 0);
    issue(1, 1);

    // ldmatrix per-lane components
    const int a_lrow0 = wm + (lane & 15);
    const int a_c16   = lane >> 4;            // 0/1
    const int b_g     = lane >> 3;            // 0..3
    const int b_lrow0 = wn + ((b_g >> 1) << 3) + (lane & 7);
    const int b_c16   = b_g & 1;

    const int NIT = INDIM / 64;   // 6
    for (int it = 0; it < NIT; it++) {
        if (it < NIT - 1) asm volatile("cp.async.wait_group 1;\n" ::: "memory");
        else              asm volatile("cp.async.wait_group 0;\n" ::: "memory");
        __syncthreads();
        if (it + 2 < NIT) issue(it + 2, (it + 2) % 3);

        const uint32_t stage_a = sbase + (uint32_t)((it % 3) * GSTAGE_W) * 4u;
        const uint32_t stage_b = stage_a + (uint32_t)GA_STAGE * 4u;

#pragma unroll
        for (int kc = 0; kc < 4; kc++) {
            uint32_t af[2][4];
#pragma unroll
            for (int mi = 0; mi < 2; mi++) {
                int row = a_lrow0 + mi * 16;
                int ch  = (kc * 2 + a_c16) ^ (row & 7);
                uint32_t addr = stage_a + (uint32_t)(row * 128 + ch * 16);
                ldmatrix_x4(af[mi], addr);
            }
            uint32_t bf[4][2];
#pragma unroll
            for (int nj = 0; nj < 2; nj++) {
                int row = b_lrow0 + nj * 16;
                int ch  = (kc * 2 + b_c16) ^ (row & 7);
                uint32_t addr = stage_b + (uint32_t)(row * 128 + ch * 16);
                uint32_t r[4];
                ldmatrix_x4(r, addr);
                bf[2*nj][0] = r[0]; bf[2*nj][1] = r[1];
                bf[2*nj+1][0] = r[2]; bf[2*nj+1][1] = r[3];
            }
#pragma unroll
            for (int mi = 0; mi < 2; mi++)
#pragma unroll
                for (int ni = 0; ni < 4; ni++)
                    mma_f16(acc[mi][ni], af[mi], bf[ni]);
        }
    }

    // BN epilogue
#pragma unroll
    for (int ni = 0; ni < 4; ni++) {
        int n0 = bn + wn + ni * 8 + 2 * tg;
        float sc0 = bn_g[n0] * rsqrtf(bn_v[n0] + BN_EPS);
        float bi0 = bn_b[n0] - bn_m[n0] * sc0;
        float sc1 = bn_g[n0 + 1] * rsqrtf(bn_v[n0 + 1] + BN_EPS);
        float bi1 = bn_b[n0 + 1] - bn_m[n0 + 1] * sc1;
#pragma unroll
        for (int mi = 0; mi < 2; mi++) {
#pragma unroll
            for (int rr = 0; rr < 2; rr++) {
                int mrow = bm + wm + mi * 16 + g8 + rr * 8;
                float vx = fmaf(acc[mi][ni][rr * 2 + 0], sc0, bi0);
                float vy = fmaf(acc[mi][ni][rr * 2 + 1], sc1, bi1);
                if (HOUT) {
                    __half2 hv = __floats2half2_rn(vx, vy);
                    *(uint32_t*)((__half*)Cv + (size_t)mrow * N + n0) = *(uint32_t*)&hv;
                } else {
                    *(float2*)((float*)Cv + (size_t)mrow * N + n0) = make_float2(vx, vy);
                }
            }
        }
    }
}

// ---------------------------------------------------------------------------
// Precompute bias table
// ---------------------------------------------------------------------------
__global__ __launch_bounds__(256)
void bias_pre_kernel(const float* __restrict__ biases, const int* __restrict__ idxs,
                     float* __restrict__ tab)
{
    int i = blockIdx.x * 256 + threadIdx.x;
    if (i < NQTOK * NTOK) {
        int id = idxs[i];
#pragma unroll
        for (int h = 0; h < HEADS; h++)
            tab[(size_t)h * (NQTOK * NTOK) + i] = biases[h * NTOK + id];
    }
}

// ---------------------------------------------------------------------------
// fp16 tensor-core attention (unchanged from R13/R15 passing version).
// ---------------------------------------------------------------------------
#define QROWS 32
#define LDK 12
#define LDVT 108
#define LDP 108
#define LDS_ 201
#define LDVN 17
#define QS_OFF 0
#define KS_OFF (QS_OFF + QROWS*LDK)
#define VT_OFF (KS_OFF + 200*LDK)
#define SB_OFF (VT_OFF + 32*LDVT)
#define PB_OFF (SB_OFF + QROWS*LDS_)
#define ATTN_SMEM_U32 (PB_OFF + QROWS*LDP)
#define ATTN_SMEM_BYTES (ATTN_SMEM_U32 * 4)

__global__ __launch_bounds__(256)
void attn_h_kernel(const __half* __restrict__ kv, const __half* __restrict__ qg,
                   const float* __restrict__ btab, __half* __restrict__ ao)
{
    extern __shared__ uint32_t sm[];
    uint32_t* Qs = sm + QS_OFF;
    uint32_t* Ks = sm + KS_OFF;
    uint32_t* Vt = sm + VT_OFF;
    uint32_t* Sb = sm + SB_OFF;
    uint32_t* Pb = sm + PB_OFF;
    uint32_t* Vn = Sb;

    const int tid   = threadIdx.x;
    const int half_ = blockIdx.x & 1;
    const int bh    = blockIdx.x >> 1;
    const int b     = bh / HEADS;
    const int h     = bh - b * HEADS;
    const int qbase = half_ * QROWS;
    const int w     = tid >> 5;
    const int lane  = tid & 31;
    const int g8    = lane >> 2;
    const int tg    = lane & 3;
    const float* bt = btab + (size_t)h * (NQTOK * NTOK);

    for (int i = tid; i < QROWS * LDK; i += 256) Qs[i] = 0;
    for (int i = tid; i < 4 * LDK; i += 256) Ks[196 * LDK + i] = 0;
    __syncthreads();

    for (int i = tid; i < QROWS * 8; i += 256) {
        int qi = i >> 3, d2 = i & 7;
        if (qbase + qi < NQTOK)
            Qs[qi * LDK + d2] =
                ((const uint32_t*)(qg + (size_t)(b * NQTOK + qbase + qi) * KEYATTN + h * KD))[d2];
    }
    for (int i = tid; i < NTOK * 8; i += 256) {
        int n = i >> 3, d2 = i & 7;
        Ks[n * LDK + d2] =
            ((const uint32_t*)(kv + (size_t)(b * NTOK + n) * KVD + h * (KD + VD)))[d2];
    }
    for (int i = tid; i < NTOK * 16; i += 256) {
        int n = i >> 4, d2 = i & 15;
        Vn[n * LDVN + d2] =
            ((const uint32_t*)(kv + (size_t)(b * NTOK + n) * KVD + h * (KD + VD) + KD))[d2];
    }
    __syncthreads();

    {
        const __half* Vnh = (const __half*)Vn;
        for (int i = tid; i < 32 * 104; i += 256) {
            int d = i / 104, p = i - (i / 104) * 104;
            uint32_t v = 0;
            if (2 * p + 1 < NTOK) {
                __half2 hv = __halves2half2(Vnh[(2 * p) * (2 * LDVN) + d],
                                            Vnh[(2 * p + 1) * (2 * LDVN) + d]);
                v = *(uint32_t*)&hv;
            }
            Vt[d * LDVT + p] = v;
        }
    }
    __syncthreads();

    {
        const int mt = w >> 2;
        const int nq = w & 3;
        const int nt0 = (nq == 0) ? 0 : (nq == 1) ? 6 : (nq == 2) ? 12 : 18;
        const int nt1 = (nq == 0) ? 6 : (nq == 1) ? 12 : (nq == 2) ? 18 : 25;

        const int r = mt * 16 + g8;
        uint32_t a[4];
        a[0] = Qs[r * LDK + tg];
        a[1] = Qs[(r + 8) * LDK + tg];
        a[2] = Qs[r * LDK + tg + 4];
        a[3] = Qs[(r + 8) * LDK + tg + 4];

        for (int nt = nt0; nt < nt1; nt++) {
            float c[4] = {0.f, 0.f, 0.f, 0.f};
            uint32_t bfr[2];
            bfr[0] = Ks[(nt * 8 + g8) * LDK + tg];
            bfr[1] = Ks[(nt * 8 + g8) * LDK + tg + 4];
            mma_f16(c, a, bfr);

            int r0 = mt * 16 + g8;
            int r1 = r0 + 8;
            int gq0 = qbase + r0;
            int gq1 = qbase + r1;
            int col = nt * 8 + 2 * tg;
            float2 bv0 = make_float2(0.f, 0.f), bv1 = make_float2(0.f, 0.f);
            if (col < NTOK) {
                if (gq0 < NQTOK) bv0 = *(const float2*)(bt + gq0 * NTOK + col);
                if (gq1 < NQTOK) bv1 = *(const float2*)(bt + gq1 * NTOK + col);
            }
            Sb[r0 * LDS_ + col]     = __float_as_uint(fmaf(c[0], ATTNSCALE, bv0.x));
            Sb[r0 * LDS_ + col + 1] = __float_as_uint(fmaf(c[1], ATTNSCALE, bv0.y));
            Sb[r1 * LDS_ + col]     = __float_as_uint(fmaf(c[2], ATTNSCALE, bv1.x));
            Sb[r1 * LDS_ + col + 1] = __float_as_uint(fmaf(c[3], ATTNSCALE, bv1.y));
        }
    }
    __syncthreads();

    for (int r = w; r < QROWS; r += 8) {
        float s0[4], s1[4];
        float mx = -1e30f;
#pragma unroll
        for (int it = 0; it < 4; it++) {
            int p = lane + it * 32;
            if (p < 98) {
                s0[it] = __uint_as_float(Sb[r * LDS_ + 2 * p]);
                s1[it] = __uint_as_float(Sb[r * LDS_ + 2 * p + 1]);
                mx = fmaxf(mx, fmaxf(s0[it], s1[it]));
            } else {
                s0[it] = -1e30f; s1[it] = -1e30f;
            }
        }
#pragma unroll
        for (int o = 16; o > 0; o >>= 1)
            mx = fmaxf(mx, __shfl_xor_sync(0xffffffffu, mx, o));
        float sum = 0.f;
        float e0[4], e1[4];
#pragma unroll
        for (int it = 0; it < 4; it++) {
            int p = lane + it * 32;
            if (p < 98) {
                e0[it] = __expf(s0[it] - mx);
                e1[it] = __expf(s1[it] - mx);
                sum += e0[it] + e1[it];
            } else { e0[it] = 0.f; e1[it] = 0.f; }
        }
#pragma unroll
        for (int o = 16; o > 0; o >>= 1)
            sum += __shfl_xor_sync(0xffffffffu, sum, o);
        float inv = 1.f / sum;
#pragma unroll
        for (int it = 0; it < 4; it++) {
            int p = lane + it * 32;
            if (p < 104) {
                __half2 hv = __floats2half2_rn(e0[it] * inv, e1[it] * inv);
                Pb[r * LDP + p] = *(uint32_t*)&hv;
            }
        }
    }
    __syncthreads();

    {
        const int mt = w >> 2;
        const int dh = w & 3;
        const int r = mt * 16 + g8;
        float acc[4] = {0.f, 0.f, 0.f, 0.f};
#pragma unroll
        for (int ks = 0; ks < 13; ks++) {
            int ku = ks * 8;
            uint32_t a[4];
            a[0] = Pb[r * LDP + ku + tg];
            a[1] = Pb[(r + 8) * LDP + ku + tg];
            a[2] = Pb[r * LDP + ku + tg + 4];
            a[3] = Pb[(r + 8) * LDP + ku + tg + 4];
            uint32_t bfr[2];
            bfr[0] = Vt[(dh * 8 + g8) * LDVT + ku + tg];
            bfr[1] = Vt[(dh * 8 + g8) * LDVT + ku + tg + 4];
            mma_f16(acc, a, bfr);
        }
        int d0  = dh * 8 + 2 * tg;
        int gq0 = qbase + mt * 16 + g8;
        int gq1 = gq0 + 8;
        if (gq0 < NQTOK) {
            float o0 = acc[0], o1 = acc[1];
            __half2 v = __floats2half2_rn(o0 / (1.f + __expf(-o0)),
                                          o1 / (1.f + __expf(-o1)));
            *(uint32_t*)(ao + (size_t)(b * NQTOK + gq0) * VALATTN + h * VD + d0) =
                *(uint32_t*)&v;
        }
        if (gq1 < NQTOK) {
            float o0 = acc[2], o1 = acc[3];
            __half2 v = __floats2half2_rn(o0 / (1.f + __expf(-o0)),
                                          o1 / (1.f + __expf(-o1)));
            *(uint32_t*)(ao + (size_t)(b * NQTOK + gq1) * VALATTN + h * VD + d0) =
                *(uint32_t*)&v;
        }
    }
}

// ---------------------------------------------------------------------------
// Launch
// ---------------------------------------------------------------------------
extern "C" void kernel_launch(void* const* d_in, const int* in_sizes, int n_in,
                              void* d_out, int out_size)
{
    const float* x     = (const float*)d_in[0];
    const float* kv_w  = (const float*)d_in[1];
    const float* kv_g  = (const float*)d_in[2];
    const float* kv_b  = (const float*)d_in[3];
    const float* kv_m  = (const float*)d_in[4];
    const float* kv_v  = (const float*)d_in[5];
    const float* q_w   = (const float*)d_in[6];
    const float* q_g   = (const float*)d_in[7];
    const float* q_b   = (const float*)d_in[8];
    const float* q_m   = (const float*)d_in[9];
    const float* q_v   = (const float*)d_in[10];
    const float* pj_w  = (const float*)d_in[11];
    const float* pj_g  = (const float*)d_in[12];
    const float* pj_b  = (const float*)d_in[13];
    const float* pj_m  = (const float*)d_in[14];
    const float* pj_v  = (const float*)d_in[15];
    const float* biases    = (const float*)d_in[16];
    const int*   bias_idxs = (const int*)d_in[17];
    float* out = (float*)d_out;

    float  *btab;
    __half *kvh, *qh, *aoh, *xh, *wh;
    cudaGetSymbolAddress((void**)&kvh,  g_kvh);
    cudaGetSymbolAddress((void**)&qh,   g_qh);
    cudaGetSymbolAddress((void**)&aoh,  g_aoh);
    cudaGetSymbolAddress((void**)&btab, g_btab);
    cudaGetSymbolAddress((void**)&xh,   g_xh);
    cudaGetSymbolAddress((void**)&wh,   g_wh);

    cudaFuncSetAttribute(attn_h_kernel,
                         cudaFuncAttributeMaxDynamicSharedMemorySize, ATTN_SMEM_BYTES);
    cudaFuncSetAttribute(gemm_h_bn<false, true>,
                         cudaFuncAttributeMaxDynamicSharedMemorySize, GEMM_SMEM_BYTES);
    cudaFuncSetAttribute(gemm_h_bn<true, true>,
                         cudaFuncAttributeMaxDynamicSharedMemorySize, GEMM_SMEM_BYTES);
    cudaFuncSetAttribute(gemm_h_bn<false, false>,
                         cudaFuncAttributeMaxDynamicSharedMemorySize, GEMM_SMEM_BYTES);

    conv_all_kernel<<<(N4_ALL + 255) / 256, 256>>>(
        (const float4*)x, (const float4*)kv_w, (const float4*)q_w, (const float4*)pj_w,
        (uint2*)xh, (uint2*)wh);

    bias_pre_kernel<<<(NQTOK * NTOK + 255) / 256, 256>>>(biases, bias_idxs, btab);

    // GEMM1: kv = BN(x @ kv_w^T)   [50176 x 576] -> fp16
    gemm_h_bn<false, true><<<dim3(KVD / 64, M1 / 128), 256, GEMM_SMEM_BYTES>>>(
        xh, wh + WR_KV, kv_g, kv_b, kv_m, kv_v, kvh, KVD);

    // GEMM2: q = BN(xq @ q_w^T)    [12544 x 192] -> fp16, gathered rows
    gemm_h_bn<true, true><<<dim3(KEYATTN / 64, M2 / 128), 256, GEMM_SMEM_BYTES>>>(
        xh, wh + WR_Q, q_g, q_b, q_m, q_v, qh, KEYATTN);

    // Attention (fp16 mma), writes fp16
    attn_h_kernel<<<BATCH * HEADS * 2, 256, ATTN_SMEM_BYTES>>>(
        kvh, qh, btab, aoh);

    // GEMM3: out = BN(silu_attn @ pj_w^T)  [12544 x 512] -> f32
    gemm_h_bn<false, false><<<dim3(OUTDIM / 64, M2 / 128), 256, GEMM_SMEM_BYTES>>>(
        aoh, wh + WR_PJ, pj_g, pj_b, pj_m, pj_v, out, OUTDIM);
}

// round 17
// speedup vs baseline: 1.9252x; 1.2955x over previous
#include <cuda_runtime.h>
#include <cuda_fp16.h>
#include <math.h>
#include <stdint.h>

// ---------------------------------------------------------------------------
// Problem constants
// ---------------------------------------------------------------------------
#define BATCH    256
#define RESOL    14
#define NTOK     196
#define NQTOK    49
#define INDIM    384
#define HEADS    12
#define KD       16
#define VD       32
#define KVD      576
#define KEYATTN  192
#define VALATTN  384
#define OUTDIM   512
#define ATTNSCALE 0.25f
#define BN_EPS   1e-5f

#define M1 (BATCH*NTOK)   // 50176
#define M2 (BATCH*NQTOK)  // 12544

#define WR_KV 0
#define WR_Q  (576*INDIM)
#define WR_PJ (768*INDIM)

// Scratch (device globals)
__device__ __half g_kvh[(size_t)M1 * KVD];
__device__ __half g_qh [(size_t)M2 * KEYATTN];
__device__ __half g_aoh[(size_t)M2 * VALATTN];
__device__ float  g_btab[(size_t)HEADS * NQTOK * NTOK];
__device__ __half g_xh [(size_t)M1 * INDIM];
__device__ __half g_wh [(size_t)1280 * INDIM];

// ---------------------------------------------------------------------------
// helpers
// ---------------------------------------------------------------------------
__device__ __forceinline__ void mma_f16(float* c, const uint32_t* a, const uint32_t* b) {
    asm volatile(
        "mma.sync.aligned.m16n8k16.row.col.f32.f16.f16.f32 "
        "{%0,%1,%2,%3}, {%4,%5,%6,%7}, {%8,%9}, {%0,%1,%2,%3};\n"
        : "+f"(c[0]), "+f"(c[1]), "+f"(c[2]), "+f"(c[3])
        : "r"(a[0]), "r"(a[1]), "r"(a[2]), "r"(a[3]), "r"(b[0]), "r"(b[1]));
}

__device__ __forceinline__ void ldmatrix_x4(uint32_t* r, uint32_t addr) {
    asm volatile("ldmatrix.sync.aligned.m8n8.x4.shared.b16 {%0,%1,%2,%3}, [%4];"
                 : "=r"(r[0]), "=r"(r[1]), "=r"(r[2]), "=r"(r[3]) : "r"(addr));
}

__device__ __forceinline__ void cp_async16(uint32_t dst, const void* src) {
    asm volatile("cp.async.cg.shared.global [%0], [%1], 16;\n" :: "r"(dst), "l"(src));
}
__device__ __forceinline__ void cp_commit() {
    asm volatile("cp.async.commit_group;\n" ::: "memory");
}

// ---------------------------------------------------------------------------
// Merged f32 -> f16 conversion (x + 3 weights), one launch
// ---------------------------------------------------------------------------
#define N4_X   ((M1*INDIM)/4)
#define N4_KV  ((KVD*INDIM)/4)
#define N4_Q   ((KEYATTN*INDIM)/4)
#define N4_PJ  ((OUTDIM*INDIM)/4)
#define N4_ALL (N4_X + N4_KV + N4_Q + N4_PJ)

__global__ __launch_bounds__(256)
void conv_all_kernel(const float4* __restrict__ x,  const float4* __restrict__ kvw,
                     const float4* __restrict__ qw, const float4* __restrict__ pjw,
                     uint2* __restrict__ xh, uint2* __restrict__ wh)
{
    int i = blockIdx.x * 256 + threadIdx.x;
    if (i >= N4_ALL) return;
    const float4* src;
    uint2* dst;
    int j = i;
    if (j < N4_X)                    { src = x;   dst = xh;                 }
    else if ((j -= N4_X) < N4_KV)    { src = kvw; dst = wh + WR_KV/4;       }
    else if ((j -= N4_KV) < N4_Q)    { src = qw;  dst = wh + WR_Q/4;        }
    else { j -= N4_Q;                  src = pjw; dst = wh + WR_PJ/4;       }
    float4 v = src[j];
    __half2 h0 = __floats2half2_rn(v.x, v.y);
    __half2 h1 = __floats2half2_rn(v.z, v.w);
    uint2 o;
    o.x = *(uint32_t*)&h0;
    o.y = *(uint32_t*)&h1;
    dst[j] = o;
}

// ---------------------------------------------------------------------------
// cp.async 3-stage fp16 GEMM, BM=128 x BN=64, BK=64, ldmatrix + XOR swizzle.
// (unchanged from R16 passing version)
// ---------------------------------------------------------------------------
#define GROW 32
#define GA_STAGE (128*GROW)
#define GB_STAGE (64*GROW)
#define GSTAGE_W (GA_STAGE + GB_STAGE)
#define GEMM_SMEM_BYTES (3*GSTAGE_W*4)

template<bool GATHER, bool HOUT>
__global__ __launch_bounds__(256)
void gemm_h_bn(const __half* __restrict__ A, const __half* __restrict__ W,
               const float* __restrict__ bn_g, const float* __restrict__ bn_b,
               const float* __restrict__ bn_m, const float* __restrict__ bn_v,
               void* __restrict__ Cv, int N)
{
    extern __shared__ uint32_t gsm[];

    const int tid  = threadIdx.x;
    const int bm   = blockIdx.y * 128;
    const int bn   = blockIdx.x * 64;
    const int warp = tid >> 5;
    const int lane = tid & 31;
    const int wm   = (warp >> 1) * 32;
    const int wn   = (warp & 1) * 32;
    const int g8   = lane >> 2;
    const int tg   = lane & 3;

    const int lrow = tid >> 3;
    const int seg  = tid & 7;

    int asrc[4];
#pragma unroll
    for (int j = 0; j < 4; j++) {
        int m = bm + lrow + 32 * j;
        if (GATHER) {
            int b  = m / NQTOK;
            int qq = m - b * NQTOK;
            int qi = qq / 7;
            int qj = qq - qi * 7;
            asrc[j] = b * NTOK + qi * 2 * RESOL + qj * 2;
        } else {
            asrc[j] = m;
        }
    }

    const uint32_t sbase = (uint32_t)__cvta_generic_to_shared(gsm);

    auto issue = [&](int it, int s) {
        const int k0 = it * 64;
        uint32_t abase = sbase + (uint32_t)(s * GSTAGE_W) * 4u;
#pragma unroll
        for (int j = 0; j < 4; j++) {
            int row = lrow + 32 * j;
            int sw  = seg ^ (row & 7);
            uint32_t dst = abase + (uint32_t)(row * 128 + sw * 16);
            cp_async16(dst, A + (size_t)asrc[j] * INDIM + k0 + seg * 8);
        }
        uint32_t bbase = abase + (uint32_t)GA_STAGE * 4u;
#pragma unroll
        for (int j = 0; j < 2; j++) {
            int row = lrow + 32 * j;
            int sw  = seg ^ (row & 7);
            uint32_t dst = bbase + (uint32_t)(row * 128 + sw * 16);
            cp_async16(dst, W + (size_t)(bn + row) * INDIM + k0 + seg * 8);
        }
        cp_commit();
    };

    float acc[2][4][4] = {};

    issue(0, 0);
    issue(1, 1);

    const int a_lrow0 = wm + (lane & 15);
    const int a_c16   = lane >> 4;
    const int b_g     = lane >> 3;
    const int b_lrow0 = wn + ((b_g >> 1) << 3) + (lane & 7);
    const int b_c16   = b_g & 1;

    const int NIT = INDIM / 64;
    for (int it = 0; it < NIT; it++) {
        if (it < NIT - 1) asm volatile("cp.async.wait_group 1;\n" ::: "memory");
        else              asm volatile("cp.async.wait_group 0;\n" ::: "memory");
        __syncthreads();
        if (it + 2 < NIT) issue(it + 2, (it + 2) % 3);

        const uint32_t stage_a = sbase + (uint32_t)((it % 3) * GSTAGE_W) * 4u;
        const uint32_t stage_b = stage_a + (uint32_t)GA_STAGE * 4u;

#pragma unroll
        for (int kc = 0; kc < 4; kc++) {
            uint32_t af[2][4];
#pragma unroll
            for (int mi = 0; mi < 2; mi++) {
                int row = a_lrow0 + mi * 16;
                int ch  = (kc * 2 + a_c16) ^ (row & 7);
                uint32_t addr = stage_a + (uint32_t)(row * 128 + ch * 16);
                ldmatrix_x4(af[mi], addr);
            }
            uint32_t bf[4][2];
#pragma unroll
            for (int nj = 0; nj < 2; nj++) {
                int row = b_lrow0 + nj * 16;
                int ch  = (kc * 2 + b_c16) ^ (row & 7);
                uint32_t addr = stage_b + (uint32_t)(row * 128 + ch * 16);
                uint32_t r[4];
                ldmatrix_x4(r, addr);
                bf[2*nj][0] = r[0]; bf[2*nj][1] = r[1];
                bf[2*nj+1][0] = r[2]; bf[2*nj+1][1] = r[3];
            }
#pragma unroll
            for (int mi = 0; mi < 2; mi++)
#pragma unroll
                for (int ni = 0; ni < 4; ni++)
                    mma_f16(acc[mi][ni], af[mi], bf[ni]);
        }
    }

#pragma unroll
    for (int ni = 0; ni < 4; ni++) {
        int n0 = bn + wn + ni * 8 + 2 * tg;
        float sc0 = bn_g[n0] * rsqrtf(bn_v[n0] + BN_EPS);
        float bi0 = bn_b[n0] - bn_m[n0] * sc0;
        float sc1 = bn_g[n0 + 1] * rsqrtf(bn_v[n0 + 1] + BN_EPS);
        float bi1 = bn_b[n0 + 1] - bn_m[n0 + 1] * sc1;
#pragma unroll
        for (int mi = 0; mi < 2; mi++) {
#pragma unroll
            for (int rr = 0; rr < 2; rr++) {
                int mrow = bm + wm + mi * 16 + g8 + rr * 8;
                float vx = fmaf(acc[mi][ni][rr * 2 + 0], sc0, bi0);
                float vy = fmaf(acc[mi][ni][rr * 2 + 1], sc1, bi1);
                if (HOUT) {
                    __half2 hv = __floats2half2_rn(vx, vy);
                    *(uint32_t*)((__half*)Cv + (size_t)mrow * N + n0) = *(uint32_t*)&hv;
                } else {
                    *(float2*)((float*)Cv + (size_t)mrow * N + n0) = make_float2(vx, vy);
                }
            }
        }
    }
}

// ---------------------------------------------------------------------------
// Precompute bias table
// ---------------------------------------------------------------------------
__global__ __launch_bounds__(256)
void bias_pre_kernel(const float* __restrict__ biases, const int* __restrict__ idxs,
                     float* __restrict__ tab)
{
    int i = blockIdx.x * 256 + threadIdx.x;
    if (i < NQTOK * NTOK) {
        int id = idxs[i];
#pragma unroll
        for (int h = 0; h < HEADS; h++)
            tab[(size_t)h * (NQTOK * NTOK) + i] = biases[h * NTOK + id];
    }
}

// ---------------------------------------------------------------------------
// Flash-style fp16 attention: ONE block per (b,h), 256 threads = 8 warps.
// Warp pair (mt = w>>1) covers 16 q-rows; halves split n-tiles 12/13.
// S kept in registers; QK C-frags pack directly into PV A-frags.
// Smem: Qs[64][12], Ks[200][12], Vt[32][108], Vn scratch (reused as
// obuf 2048 f32 + red 256 f32 after transpose).
// ---------------------------------------------------------------------------
#define ALDK 12
#define ALDVT 108
#define ALDVN 17
#define AQS_OFF 0
#define AKS_OFF 768
#define AVT_OFF 3168
#define AVN_OFF 6624
#define ARED_F32 2048                       // float index into Vn region
#define ATTN_SMEM_U32 (AVN_OFF + 3332)      // 9956
#define ATTN_SMEM_BYTES (ATTN_SMEM_U32 * 4) // 39824

__global__ __launch_bounds__(256)
void attn_h_kernel(const __half* __restrict__ kv, const __half* __restrict__ qg,
                   const float* __restrict__ btab, __half* __restrict__ ao)
{
    extern __shared__ uint32_t sm[];
    uint32_t* Qs = sm + AQS_OFF;
    uint32_t* Ks = sm + AKS_OFF;
    uint32_t* Vt = sm + AVT_OFF;
    uint32_t* Vn = sm + AVN_OFF;
    float*    ob  = (float*)(sm + AVN_OFF);          // obuf [4][32][16]
    float*    red = (float*)(sm + AVN_OFF) + ARED_F32; // [256]

    const int tid  = threadIdx.x;
    const int b    = blockIdx.x / HEADS;
    const int h    = blockIdx.x - b * HEADS;
    const int w    = tid >> 5;
    const int lane = tid & 31;
    const int g8   = lane >> 2;
    const int tg   = lane & 3;
    const int mt   = w >> 1;
    const int half_ = w & 1;
    const float* bt = btab + (size_t)h * (NQTOK * NTOK);

    // ---- stage Q (zero-fill rows >= 49) ----
    for (int i = tid; i < 64 * 8; i += 256) {
        int qi = i >> 3, d2 = i & 7;
        uint32_t v = 0;
        if (qi < NQTOK)
            v = ((const uint32_t*)(qg + (size_t)(b * NQTOK + qi) * KEYATTN + h * KD))[d2];
        Qs[qi * ALDK + d2] = v;
    }
    // ---- stage K (zero-fill rows 196..199) ----
    for (int i = tid; i < 200 * 8; i += 256) {
        int n = i >> 3, d2 = i & 7;
        uint32_t v = 0;
        if (n < NTOK)
            v = ((const uint32_t*)(kv + (size_t)(b * NTOK + n) * KVD + h * (KD + VD)))[d2];
        Ks[n * ALDK + d2] = v;
    }
    // ---- stage V rows coalesced ----
    for (int i = tid; i < NTOK * 16; i += 256) {
        int n = i >> 4, d2 = i & 15;
        Vn[n * ALDVN + d2] =
            ((const uint32_t*)(kv + (size_t)(b * NTOK + n) * KVD + h * (KD + VD) + KD))[d2];
    }
    __syncthreads();

    // ---- transpose V in smem ----
    {
        const __half* Vnh = (const __half*)Vn;
        for (int i = tid; i < 32 * 104; i += 256) {
            int d = i / 104, p = i - (i / 104) * 104;
            uint32_t v = 0;
            if (2 * p + 1 < NTOK) {
                __half2 hv = __halves2half2(Vnh[(2 * p) * (2 * ALDVN) + d],
                                            Vnh[(2 * p + 1) * (2 * ALDVN) + d]);
                v = *(uint32_t*)&hv;
            }
            Vt[d * ALDVT + p] = v;
        }
    }
    __syncthreads();   // Vn dead after this; ob/red live in its space

    // ---- QK + bias, S in registers ----
    const int NT0 = half_ ? 12 : 0;
    const int NTN = half_ ? 13 : 12;
    const int gq0 = mt * 16 + g8;
    const int gq1 = gq0 + 8;

    float s[13][4];
    {
        uint32_t a[4];
        int r = mt * 16 + g8;
        a[0] = Qs[r * ALDK + tg];
        a[1] = Qs[(r + 8) * ALDK + tg];
        a[2] = Qs[r * ALDK + tg + 4];
        a[3] = Qs[(r + 8) * ALDK + tg + 4];
#pragma unroll
        for (int t = 0; t < 13; t++) {
            if (t < NTN) {
                int nt = NT0 + t;
                float c[4] = {0.f, 0.f, 0.f, 0.f};
                uint32_t bfr[2];
                bfr[0] = Ks[(nt * 8 + g8) * ALDK + tg];
                bfr[1] = Ks[(nt * 8 + g8) * ALDK + tg + 4];
                mma_f16(c, a, bfr);
                int col = nt * 8 + 2 * tg;
                if (col < NTOK) {
                    float2 bv0 = (gq0 < NQTOK) ? *(const float2*)(bt + gq0 * NTOK + col)
                                               : make_float2(0.f, 0.f);
                    float2 bv1 = (gq1 < NQTOK) ? *(const float2*)(bt + gq1 * NTOK + col)
                                               : make_float2(0.f, 0.f);
                    s[t][0] = fmaf(c[0], ATTNSCALE, bv0.x);
                    s[t][1] = fmaf(c[1], ATTNSCALE, bv0.y);
                    s[t][2] = fmaf(c[2], ATTNSCALE, bv1.x);
                    s[t][3] = fmaf(c[3], ATTNSCALE, bv1.y);
                } else {
                    s[t][0] = s[t][1] = s[t][2] = s[t][3] = -1e30f;
                }
            } else {
                s[t][0] = s[t][1] = s[t][2] = s[t][3] = -1e30f;
            }
        }
    }

    // ---- softmax: row max (intra-warp shuffle + cross-half smem) ----
    float mx0 = -1e30f, mx1 = -1e30f;
#pragma unroll
    for (int t = 0; t < 13; t++) {
        mx0 = fmaxf(mx0, fmaxf(s[t][0], s[t][1]));
        mx1 = fmaxf(mx1, fmaxf(s[t][2], s[t][3]));
    }
    mx0 = fmaxf(mx0, __shfl_xor_sync(0xffffffffu, mx0, 1));
    mx0 = fmaxf(mx0, __shfl_xor_sync(0xffffffffu, mx0, 2));
    mx1 = fmaxf(mx1, __shfl_xor_sync(0xffffffffu, mx1, 1));
    mx1 = fmaxf(mx1, __shfl_xor_sync(0xffffffffu, mx1, 2));
    if (tg == 0) {
        red[mt * 32 + g8 * 2 + half_]       = mx0;
        red[mt * 32 + (g8 + 8) * 2 + half_] = mx1;
    }
    __syncthreads();
    mx0 = fmaxf(red[mt * 32 + g8 * 2], red[mt * 32 + g8 * 2 + 1]);
    mx1 = fmaxf(red[mt * 32 + (g8 + 8) * 2], red[mt * 32 + (g8 + 8) * 2 + 1]);

    // ---- exp + row sum ----
    float sum0 = 0.f, sum1 = 0.f;
#pragma unroll
    for (int t = 0; t < 13; t++) {
        s[t][0] = __expf(s[t][0] - mx0);
        s[t][1] = __expf(s[t][1] - mx0);
        s[t][2] = __expf(s[t][2] - mx1);
        s[t][3] = __expf(s[t][3] - mx1);
        sum0 += s[t][0] + s[t][1];
        sum1 += s[t][2] + s[t][3];
    }
    sum0 += __shfl_xor_sync(0xffffffffu, sum0, 1);
    sum0 += __shfl_xor_sync(0xffffffffu, sum0, 2);
    sum1 += __shfl_xor_sync(0xffffffffu, sum1, 1);
    sum1 += __shfl_xor_sync(0xffffffffu, sum1, 2);
    if (tg == 0) {
        red[128 + mt * 32 + g8 * 2 + half_]       = sum0;
        red[128 + mt * 32 + (g8 + 8) * 2 + half_] = sum1;
    }
    __syncthreads();
    float inv0 = 1.f / (red[128 + mt * 32 + g8 * 2] + red[128 + mt * 32 + g8 * 2 + 1]);
    float inv1 = 1.f / (red[128 + mt * 32 + (g8 + 8) * 2] + red[128 + mt * 32 + (g8 + 8) * 2 + 1]);

    // ---- pack P to fp16 pairs (= PV A-fragments) ----
    uint32_t plo[13], phi[13];
#pragma unroll
    for (int t = 0; t < 13; t++) {
        __half2 l  = __floats2half2_rn(s[t][0] * inv0, s[t][1] * inv0);
        __half2 hh = __floats2half2_rn(s[t][2] * inv1, s[t][3] * inv1);
        plo[t] = *(uint32_t*)&l;
        phi[t] = *(uint32_t*)&hh;
    }

    // ---- PV: half0 chunks 0..5, half1 chunks 6..12 ----
    float acc[4][4] = {};
    const int ksn = half_ ? 7 : 6;
#pragma unroll
    for (int kk = 0; kk < 7; kk++) {
        if (kk < ksn) {
            uint32_t a[4];
            a[0] = plo[2 * kk];
            a[1] = phi[2 * kk];
            bool hasnext = (2 * kk + 1 < NTN);
            a[2] = hasnext ? plo[2 * kk + 1] : 0u;
            a[3] = hasnext ? phi[2 * kk + 1] : 0u;
            int ku = (half_ ? 48 : 0) + kk * 8;   // pair offset into Vt
#pragma unroll
            for (int dn = 0; dn < 4; dn++) {
                uint32_t bfr[2];
                bfr[0] = Vt[(dn * 8 + g8) * ALDVT + ku + tg];
                bfr[1] = Vt[(dn * 8 + g8) * ALDVT + ku + tg + 4];
                mma_f16(acc[dn], a, bfr);
            }
        }
    }

    // ---- merge halves, silu, store ----
    if (half_ == 1) {
        float* dst = ob + (mt * 32 + lane) * 16;
#pragma unroll
        for (int dn = 0; dn < 4; dn++)
#pragma unroll
            for (int j = 0; j < 4; j++)
                dst[dn * 4 + j] = acc[dn][j];
    }
    __syncthreads();
    if (half_ == 0) {
        const float* src = ob + (mt * 32 + lane) * 16;
#pragma unroll
        for (int dn = 0; dn < 4; dn++) {
            float o0 = acc[dn][0] + src[dn * 4 + 0];
            float o1 = acc[dn][1] + src[dn * 4 + 1];
            float o2 = acc[dn][2] + src[dn * 4 + 2];
            float o3 = acc[dn][3] + src[dn * 4 + 3];
            int d0 = dn * 8 + 2 * tg;
            if (gq0 < NQTOK) {
                __half2 v = __floats2half2_rn(o0 / (1.f + __expf(-o0)),
                                              o1 / (1.f + __expf(-o1)));
                *(uint32_t*)(ao + (size_t)(b * NQTOK + gq0) * VALATTN + h * VD + d0) =
                    *(uint32_t*)&v;
            }
            if (gq1 < NQTOK) {
                __half2 v = __floats2half2_rn(o2 / (1.f + __expf(-o2)),
                                              o3 / (1.f + __expf(-o3)));
                *(uint32_t*)(ao + (size_t)(b * NQTOK + gq1) * VALATTN + h * VD + d0) =
                    *(uint32_t*)&v;
            }
        }
    }
}

// ---------------------------------------------------------------------------
// Launch
// ---------------------------------------------------------------------------
extern "C" void kernel_launch(void* const* d_in, const int* in_sizes, int n_in,
                              void* d_out, int out_size)
{
    const float* x     = (const float*)d_in[0];
    const float* kv_w  = (const float*)d_in[1];
    const float* kv_g  = (const float*)d_in[2];
    const float* kv_b  = (const float*)d_in[3];
    const float* kv_m  = (const float*)d_in[4];
    const float* kv_v  = (const float*)d_in[5];
    const float* q_w   = (const float*)d_in[6];
    const float* q_g   = (const float*)d_in[7];
    const float* q_b   = (const float*)d_in[8];
    const float* q_m   = (const float*)d_in[9];
    const float* q_v   = (const float*)d_in[10];
    const float* pj_w  = (const float*)d_in[11];
    const float* pj_g  = (const float*)d_in[12];
    const float* pj_b  = (const float*)d_in[13];
    const float* pj_m  = (const float*)d_in[14];
    const float* pj_v  = (const float*)d_in[15];
    const float* biases    = (const float*)d_in[16];
    const int*   bias_idxs = (const int*)d_in[17];
    float* out = (float*)d_out;

    float  *btab;
    __half *kvh, *qh, *aoh, *xh, *wh;
    cudaGetSymbolAddress((void**)&kvh,  g_kvh);
    cudaGetSymbolAddress((void**)&qh,   g_qh);
    cudaGetSymbolAddress((void**)&aoh,  g_aoh);
    cudaGetSymbolAddress((void**)&btab, g_btab);
    cudaGetSymbolAddress((void**)&xh,   g_xh);
    cudaGetSymbolAddress((void**)&wh,   g_wh);

    cudaFuncSetAttribute(attn_h_kernel,
                         cudaFuncAttributeMaxDynamicSharedMemorySize, ATTN_SMEM_BYTES);
    cudaFuncSetAttribute(gemm_h_bn<false, true>,
                         cudaFuncAttributeMaxDynamicSharedMemorySize, GEMM_SMEM_BYTES);
    cudaFuncSetAttribute(gemm_h_bn<true, true>,
                         cudaFuncAttributeMaxDynamicSharedMemorySize, GEMM_SMEM_BYTES);
    cudaFuncSetAttribute(gemm_h_bn<false, false>,
                         cudaFuncAttributeMaxDynamicSharedMemorySize, GEMM_SMEM_BYTES);

    conv_all_kernel<<<(N4_ALL + 255) / 256, 256>>>(
        (const float4*)x, (const float4*)kv_w, (const float4*)q_w, (const float4*)pj_w,
        (uint2*)xh, (uint2*)wh);

    bias_pre_kernel<<<(NQTOK * NTOK + 255) / 256, 256>>>(biases, bias_idxs, btab);

    // GEMM1: kv = BN(x @ kv_w^T)   [50176 x 576] -> fp16
    gemm_h_bn<false, true><<<dim3(KVD / 64, M1 / 128), 256, GEMM_SMEM_BYTES>>>(
        xh, wh + WR_KV, kv_g, kv_b, kv_m, kv_v, kvh, KVD);

    // GEMM2: q = BN(xq @ q_w^T)    [12544 x 192] -> fp16, gathered rows
    gemm_h_bn<true, true><<<dim3(KEYATTN / 64, M2 / 128), 256, GEMM_SMEM_BYTES>>>(
        xh, wh + WR_Q, q_g, q_b, q_m, q_v, qh, KEYATTN);

    // Attention (flash-style, one block per (b,h)), writes fp16
    attn_h_kernel<<<BATCH * HEADS, 256, ATTN_SMEM_BYTES>>>(
        kvh, qh, btab, aoh);

    // GEMM3: out = BN(silu_attn @ pj_w^T)  [12544 x 512] -> f32
    gemm_h_bn<false, false><<<dim3(OUTDIM / 64, M2 / 128), 256, GEMM_SMEM_BYTES>>>(
        aoh, wh + WR_PJ, pj_g, pj_b, pj_m, pj_v, out, OUTDIM);
}